// round 8
// baseline (speedup 1.0000x reference)
#include <cuda_runtime.h>
#include <cuda_bf16.h>
#include <math.h>
#include <stdint.h>

#define TT 512
#define BB 64
#define DH 1024
#define BH (BB*DH)
#define NB 128          // persistent blocks, 1/SM
#define CPB 8           // hidden columns per block

// ---------------- recurrent kernel SMEM layout (bytes) --------------------
#define RS_W    0          // 6 slabs x 16384 (WRhi,WRlo,WZhi,WZlo,WHhi,WHlo)
#define RS_A    98304      // 4 buffers x 32768 (hi 16K + lo 16K); chunk=128 kcols
#define RS_Z    229376     // z gate buf 64x8 f32 (2048 B)
#define RS_F    231424     // full[8] tokens, cons[8] tokens (64 B)
#define RS_TOT  231488

// ---------------- input gemm SMEM layout (bytes, per stage) ---------------
#define IG_AH   0
#define IG_AL   16384
#define IG_WH   32768
#define IG_WL   65536
#define IG_STG  98304
#define IG_TOT  196608

// ---------------- device globals ------------------------------------------
__device__ float g_Xr[(size_t)TT * BH];
__device__ float g_Xz[(size_t)TT * BH];
__device__ float g_Xh[(size_t)TT * BH];
__device__ __nv_bfloat16 g_X_hi[(size_t)TT * BB * DH];
__device__ __nv_bfloat16 g_X_lo[(size_t)TT * BB * DH];
__device__ __nv_bfloat16 g_W_hi[3u * 1024u * 1024u];
__device__ __nv_bfloat16 g_W_lo[3u * 1024u * 1024u];
__device__ __nv_bfloat16 g_h_hi[2][BH], g_h_lo[2][BH];
__device__ __nv_bfloat16 g_Rh_hi[2][BH], g_Rh_lo[2][BH];
__device__ unsigned g_cnt_h[8];     // h publishers per 128-col chunk (16 blocks each)
__device__ unsigned g_cnt_rh[8];    // Rh publishers per 128-col chunk
__device__ unsigned g_p1done;       // blocks done reading h (phase 1), per step
__device__ unsigned g_p2done;       // blocks done reading Rh (phase 2), per step
__device__ unsigned g_bar_count = 0;
__device__ volatile unsigned g_bar_gen = 0;

// ---------------- helpers -------------------------------------------------
__device__ __forceinline__ uint32_t smem_u32(const void* p) {
    uint32_t a;
    asm("{ .reg .u64 t; cvta.to.shared.u64 t, %1; cvt.u32.u64 %0, t; }" : "=r"(a) : "l"(p));
    return a;
}
__device__ __forceinline__ void mma16816(float* c, const uint32_t* a, const uint32_t* b) {
    asm volatile("mma.sync.aligned.m16n8k16.row.col.f32.bf16.bf16.f32 "
        "{%0,%1,%2,%3}, {%4,%5,%6,%7}, {%8,%9}, {%0,%1,%2,%3};"
        : "+f"(c[0]), "+f"(c[1]), "+f"(c[2]), "+f"(c[3])
        : "r"(a[0]), "r"(a[1]), "r"(a[2]), "r"(a[3]), "r"(b[0]), "r"(b[1]));
}
__device__ __forceinline__ void ldsm_x4(uint32_t* r, uint32_t a) {
    asm volatile("ldmatrix.sync.aligned.m8n8.x4.shared.b16 {%0,%1,%2,%3}, [%4];"
        : "=r"(r[0]), "=r"(r[1]), "=r"(r[2]), "=r"(r[3]) : "r"(a));
}
__device__ __forceinline__ void ldsm_x4t(uint32_t* r, uint32_t a) {
    asm volatile("ldmatrix.sync.aligned.m8n8.x4.trans.shared.b16 {%0,%1,%2,%3}, [%4];"
        : "=r"(r[0]), "=r"(r[1]), "=r"(r[2]), "=r"(r[3]) : "r"(a));
}
#define CPASYNC16(dst, src) asm volatile("cp.async.cg.shared.global [%0], [%1], 16;" :: "r"(dst), "l"(src))
#define CPCOMMIT() asm volatile("cp.async.commit_group;" ::: "memory")
#define CPWAIT1()  asm volatile("cp.async.wait_group 1;" ::: "memory")
#define CPWAIT0()  asm volatile("cp.async.wait_group 0;" ::: "memory")

__device__ __forceinline__ unsigned ld_acq_g(const unsigned* p) {
    unsigned v;
    asm volatile("ld.acquire.gpu.global.u32 %0, [%1];" : "=r"(v) : "l"(p) : "memory");
    return v;
}
__device__ __forceinline__ void waitGE(const unsigned* p, unsigned tgt) {
    while ((int)(ld_acq_g(p) - tgt) < 0) { }
}
__device__ __forceinline__ unsigned lds_acq(uint32_t a) {
    unsigned v;
    asm volatile("ld.acquire.cta.shared.u32 %0, [%1];" : "=r"(v) : "r"(a) : "memory");
    return v;
}
__device__ __forceinline__ void smemWaitGE(uint32_t a, unsigned tgt) {
    while ((int)(lds_acq(a) - tgt) < 0) { }
}
__device__ __forceinline__ void sts_rel(uint32_t a, unsigned v) {
    asm volatile("st.release.cta.shared.u32 [%0], %1;" :: "r"(a), "r"(v) : "memory");
}
__device__ __forceinline__ void red_rel_sh(uint32_t a, unsigned v) {
    asm volatile("red.release.cta.shared.add.u32 [%0], %1;" :: "r"(a), "r"(v) : "memory");
}
__device__ __forceinline__ void red_rel_gpu(unsigned* p, unsigned v) {
    asm volatile("red.release.gpu.global.add.u32 [%0], %1;" :: "l"(p), "r"(v) : "memory");
}

__device__ __forceinline__ uint32_t packbf(__nv_bfloat16 x, __nv_bfloat16 y) {
    unsigned short ux = *(unsigned short*)&x, uy = *(unsigned short*)&y;
    return (uint32_t)ux | ((uint32_t)uy << 16);
}
__device__ __forceinline__ void split2(float vx, float vy, uint32_t& hi, uint32_t& lo) {
    __nv_bfloat16 hx = __float2bfloat16(vx), hy = __float2bfloat16(vy);
    __nv_bfloat16 lx = __float2bfloat16(vx - __bfloat162float(hx));
    __nv_bfloat16 ly = __float2bfloat16(vy - __bfloat162float(hy));
    hi = packbf(hx, hy); lo = packbf(lx, ly);
}
__device__ __forceinline__ float sigf(float x) { return 1.0f / (1.0f + expf(-x)); }
__device__ __forceinline__ uint32_t swz32(uint32_t s, uint32_t r) {
    return ((s & 7u) ^ (r & 7u)) | (s & 24u);
}
__device__ __forceinline__ uint32_t swz16(uint32_t s, uint32_t r) {
    return ((s & 7u) ^ (r & 7u)) | (s & 8u);
}

// ---------------- grid barrier (init only) --------------------------------
__device__ __forceinline__ void gridBarrier() {
    __syncthreads();
    if (threadIdx.x == 0) {
        __threadfence();
        unsigned g = g_bar_gen;
        if (atomicAdd(&g_bar_count, 1u) == (unsigned)(NB - 1)) {
            g_bar_count = 0;
            __threadfence();
            g_bar_gen = g + 1;
        } else {
            while (g_bar_gen == g) { }
        }
        __threadfence();
    }
    __syncthreads();
}

// ---------------- prepass: fp32 -> bf16 hi/lo split -----------------------
__global__ void __launch_bounds__(256) split_pass(
    const float* __restrict__ src, __nv_bfloat16* __restrict__ hi,
    __nv_bfloat16* __restrict__ lo, int n4)
{
    int i = blockIdx.x * 256 + threadIdx.x;
    if (i >= n4) return;
    float4 v = __ldg((const float4*)src + i);
    uint32_t h0, l0, h1, l1;
    split2(v.x, v.y, h0, l0);
    split2(v.z, v.w, h1, l1);
    ((uint2*)hi)[i] = make_uint2(h0, h1);
    ((uint2*)lo)[i] = make_uint2(l0, l1);
}

// ---------------- input projection GEMM (HMMA, cp.async pipeline) ---------
__global__ void __launch_bounds__(512, 1) input_gemm(
    const float* __restrict__ br, const float* __restrict__ bz, const float* __restrict__ bh)
{
    extern __shared__ char sm[];
    const uint32_t sb = smem_u32(sm);
    const int z = blockIdx.z;
    const float* bias = (z == 0) ? br : (z == 1) ? bz : bh;
    float* Out = (z == 0) ? g_Xr : (z == 1) ? g_Xz : g_Xh;
    const __nv_bfloat16* WHi = g_W_hi + (size_t)z * 1048576u;
    const __nv_bfloat16* WLo = g_W_lo + (size_t)z * 1048576u;

    const int tid = threadIdx.x;
    const int lane = tid & 31, w = tid >> 5;
    const int rowBase = blockIdx.y * 128;
    const int colBase = blockIdx.x * 256;
    const int mw = (w & 3) * 32;
    const int nw = (w >> 2) * 64;

    float acc[2][8][4];
    #pragma unroll
    for (int i = 0; i < 2; i++)
        #pragma unroll
        for (int j = 0; j < 8; j++)
            #pragma unroll
            for (int q = 0; q < 4; q++) acc[i][j][q] = 0.f;

    auto stage = [&](int c, uint32_t bufSm) {
        const int k0 = c * 64;
        #pragma unroll
        for (int it = 0; it < 2; it++) {
            int idx = tid + it * 512;
            int r = idx >> 3, s = idx & 7;
            uint32_t d = bufSm + IG_AH + r * 128 + ((s ^ (r & 7)) * 16);
            const __nv_bfloat16* g = g_X_hi + (size_t)(rowBase + r) * 1024 + k0 + s * 8;
            CPASYNC16(d, g);
            d = bufSm + IG_AL + r * 128 + ((s ^ (r & 7)) * 16);
            g = g_X_lo + (size_t)(rowBase + r) * 1024 + k0 + s * 8;
            CPASYNC16(d, g);
        }
        #pragma unroll
        for (int it = 0; it < 4; it++) {
            int idx = tid + it * 512;
            int k = idx >> 5, s = idx & 31;
            uint32_t d = bufSm + IG_WH + k * 512 + swz32(s, k) * 16;
            const __nv_bfloat16* g = WHi + (size_t)(k0 + k) * 1024 + colBase + s * 8;
            CPASYNC16(d, g);
            d = bufSm + IG_WL + k * 512 + swz32(s, k) * 16;
            g = WLo + (size_t)(k0 + k) * 1024 + colBase + s * 8;
            CPASYNC16(d, g);
        }
    };

    stage(0, sb + 0);
    CPCOMMIT();

    for (int c = 0; c < 16; c++) {
        const uint32_t cur = sb + (uint32_t)(c & 1) * IG_STG;
        if (c < 15) {
            stage(c + 1, sb + (uint32_t)((c + 1) & 1) * IG_STG);
            CPCOMMIT();
            CPWAIT1();
        } else {
            CPWAIT0();
        }
        __syncthreads();

        #pragma unroll
        for (int ks = 0; ks < 4; ks++) {
            uint32_t ah[2][4], al[2][4];
            #pragma unroll
            for (int i = 0; i < 2; i++) {
                int row = mw + i * 16 + (lane & 15);
                int s = ks * 2 + (lane >> 4);
                uint32_t ab = cur + row * 128 + ((s ^ (row & 7)) * 16);
                ldsm_x4(ah[i], ab + IG_AH);
                ldsm_x4(al[i], ab + IG_AL);
            }
            #pragma unroll
            for (int jp = 0; jp < 4; jp++) {
                int rrow = ks * 16 + (lane & 15);
                int sc = (nw >> 3) + jp * 2 + (lane >> 4);
                uint32_t bb = cur + rrow * 512 + swz32((uint32_t)sc, (uint32_t)rrow) * 16;
                uint32_t bh[4], bl[4];
                ldsm_x4t(bh, bb + IG_WH);
                ldsm_x4t(bl, bb + IG_WL);
                #pragma unroll
                for (int i = 0; i < 2; i++) {
                    mma16816(acc[i][jp*2+0], ah[i], &bh[0]);
                    mma16816(acc[i][jp*2+0], al[i], &bh[0]);
                    mma16816(acc[i][jp*2+0], ah[i], &bl[0]);
                    mma16816(acc[i][jp*2+1], ah[i], &bh[2]);
                    mma16816(acc[i][jp*2+1], al[i], &bh[2]);
                    mma16816(acc[i][jp*2+1], ah[i], &bl[2]);
                }
            }
        }
        __syncthreads();
    }

    const int g = lane >> 2, qn = (lane & 3) * 2;
    #pragma unroll
    for (int j = 0; j < 8; j++) {
        int col = colBase + nw + j * 8 + qn;
        float2 bv = *(const float2*)(bias + col);
        #pragma unroll
        for (int i = 0; i < 2; i++) {
            int r0 = rowBase + mw + i * 16 + g;
            *(float2*)(Out + (size_t)r0 * 1024 + col) =
                make_float2(acc[i][j][0] + bv.x, acc[i][j][1] + bv.y);
            *(float2*)(Out + (size_t)(r0 + 8) * 1024 + col) =
                make_float2(acc[i][j][2] + bv.x, acc[i][j][3] + bv.y);
        }
    }
}

// ---------------- recurrent kernel (persistent, warp-specialized) ---------
// 128 blocks x 512 threads. Warps 0-7 consume (R/Z; warps 0-3 also H-hat),
// warps 8-15 each own one 128-col k-chunk and stream it via cp.async.
__global__ void __launch_bounds__(512, 1) gru_recurrent(
    const float* __restrict__ state,
    const float* __restrict__ Whr, const float* __restrict__ Whz, const float* __restrict__ Whh,
    float* __restrict__ out)
{
    extern __shared__ char sm[];
    const uint32_t sb = smem_u32(sm);
    const int tid = threadIdx.x;
    const int lane = tid & 31, w = tid >> 5;
    const int bid = blockIdx.x;
    const int cB  = bid * CPB;

    const uint32_t FULLB = sb + RS_F;        // full[8]
    const uint32_t CONSB = sb + RS_F + 32;   // cons[8]

    // ---- reset dataflow counters (block 0) + smem tokens ----
    if (bid == 0 && tid == 0) {
        #pragma unroll
        for (int c = 0; c < 8; c++) { g_cnt_h[c] = 16u; g_cnt_rh[c] = 0u; }
        g_p1done = 0u; g_p2done = 0u;
    }
    if (tid < 16) ((unsigned*)(sm + RS_F))[tid] = 0u;

    // ---- persistent W slabs: [k][8n] rows of 16B, hi/lo bf16 ----
    {
        const float* Wm[3] = { Whr, Whz, Whh };
        for (int idx = tid; idx < 8192; idx += 512) {
            int k = idx >> 3, n = idx & 7;
            #pragma unroll
            for (int m = 0; m < 3; m++) {
                float v = Wm[m][(size_t)k * 1024 + cB + n];
                __nv_bfloat16 h = __float2bfloat16(v);
                __nv_bfloat16 l = __float2bfloat16(v - __bfloat162float(h));
                *(__nv_bfloat16*)(sm + RS_W + (2*m)   * 16384 + k * 16 + n * 2) = h;
                *(__nv_bfloat16*)(sm + RS_W + (2*m+1) * 16384 + k * 16 + n * 2) = l;
            }
        }
    }
    // ---- init h (buffer 0) ----
    if (tid < 512) {
        int r = tid >> 3, n = tid & 7;
        size_t gi = (size_t)r * 1024 + cB + n;
        float v = state[gi];
        __nv_bfloat16 h = __float2bfloat16(v);
        __nv_bfloat16 l = __float2bfloat16(v - __bfloat162float(h));
        g_h_hi[0][gi] = h; g_h_lo[0][gi] = l;
    }
    gridBarrier();   // publishes resets + weights + h0

    const int m0  = (w & 3) * 16;
    const bool isR = (w < 4);
    const int g   = lane >> 2, qn = (lane & 3) * 2;
    const int r0  = m0 + g;
    const int col = cB + qn;
    const uint32_t wsel_hi = sb + RS_W + (isR ? 0 : 2) * 16384;
    const uint32_t whh_hi  = sb + RS_W + 4 * 16384;

    // per-thread fp32 h state (warps 0-3 only; thread-private addresses)
    float hv0x = 0.f, hv0y = 0.f, hv1x = 0.f, hv1y = 0.f;
    if (w < 4) {
        float2 a = *(const float2*)(state + (size_t)r0 * 1024 + col);
        float2 b = *(const float2*)(state + (size_t)(r0 + 8) * 1024 + col);
        hv0x = a.x; hv0y = a.y; hv1x = b.x; hv1y = b.y;
    }

    // ---- producer: stream chunk j (128 kcols) into ring buffer j&3 ----
    auto prodLoad = [&](const __nv_bfloat16* hi, const __nv_bfloat16* lo, int j,
                        unsigned consTgt, unsigned* gcnt, unsigned gtgt, unsigned tok) {
        if (lane == 0) {
            int jp = (j < 4) ? j + 4 : j - 4;       // chunk sharing this buffer
            smemWaitGE(CONSB + jp * 4, consTgt);
            waitGE(gcnt, gtgt);
        }
        __syncwarp();
        const uint32_t bufHi = sb + RS_A + (uint32_t)(j & 3) * 32768;
        const int k0 = j * 128;
        #pragma unroll 8
        for (int it = 0; it < 32; it++) {
            int idx = lane + it * 32;               // 0..1023
            int r = idx >> 4, s = idx & 15;
            uint32_t off = (uint32_t)r * 256u + swz16((uint32_t)s, (uint32_t)r) * 16u;
            size_t go = (size_t)r * 1024 + k0 + s * 8;
            CPASYNC16(bufHi + off, hi + go);
            CPASYNC16(bufHi + 16384 + off, lo + go);
        }
        CPCOMMIT(); CPWAIT0();
        __syncwarp();
        if (lane == 0) sts_rel(FULLB + j * 4, tok);
    };

    // ---- consumer: accumulate one chunk against a W slab ----
    auto mmaChunk = [&](float* acc, int j, uint32_t wHi) {
        const uint32_t abase = sb + RS_A + (uint32_t)(j & 3) * 32768;
        const uint32_t arow = (uint32_t)(m0 + (lane & 15));
        #pragma unroll
        for (int ks2 = 0; ks2 < 4; ks2++) {
            uint32_t bh[4], bl[4];
            uint32_t baddr = wHi + (uint32_t)(j * 128 + ks2 * 32 + lane) * 16;
            ldsm_x4t(bh, baddr);
            ldsm_x4t(bl, baddr + 16384);
            uint32_t s0 = (uint32_t)(ks2 * 4 + (lane >> 4));
            uint32_t s1 = s0 + 2;
            uint32_t a0 = abase + arow * 256u + swz16(s0, arow) * 16u;
            uint32_t a1 = abase + arow * 256u + swz16(s1, arow) * 16u;
            uint32_t ah0[4], al0[4], ah1[4], al1[4];
            ldsm_x4(ah0, a0); ldsm_x4(al0, a0 + 16384);
            ldsm_x4(ah1, a1); ldsm_x4(al1, a1 + 16384);
            mma16816(acc, ah0, &bh[0]);
            mma16816(acc, al0, &bh[0]);
            mma16816(acc, ah0, &bl[0]);
            mma16816(acc, ah1, &bh[2]);
            mma16816(acc, al1, &bh[2]);
            mma16816(acc, ah1, &bl[2]);
        }
    };

    for (int t = 0; t < TT; t++) {
        const int p = t & 1, pn = p ^ 1;
        const unsigned gtgt = 16u * (unsigned)(t + 1);
        const unsigned tok1 = (unsigned)(2 * t + 1);
        const unsigned tok2 = (unsigned)(2 * t + 2);

        // ================ phase 1: R (warps 0-3) / Z (warps 4-7) ==========
        float acc[4] = {0.f, 0.f, 0.f, 0.f};
        if (w >= 8) {
            const int j = w - 8;
            unsigned consTgt = (j < 4) ? 12u * (unsigned)t : 12u * (unsigned)t + 8u;
            prodLoad(g_h_hi[p], g_h_lo[p], j, consTgt, g_cnt_h + j, gtgt, tok1);
        } else {
            #pragma unroll 1
            for (int j = 0; j < 8; j++) {
                if (lane == 0) smemWaitGE(FULLB + j * 4, tok1);
                __syncwarp();
                mmaChunk(acc, j, wsel_hi);
                __syncwarp();
                if (lane == 0) red_rel_sh(CONSB + j * 4, 1u);
            }
            if (tid == 0) red_rel_gpu(&g_p1done, 1u);   // all h loads witnessed done
        }
        // ---- epilogue 1 ----
        if (w < 8) {
            size_t o0 = (size_t)t * BH + (size_t)r0 * 1024 + col;
            size_t o1 = o0 + 8 * 1024;
            size_t h0o = (size_t)r0 * 1024 + col, h1o = h0o + 8 * 1024;
            if (isR) {
                // WAR: Rh buf p last read in phase 2 of step t-2
                if (t >= 2) { if (lane == 0) waitGE(&g_p2done, 128u * (unsigned)(t - 1)); __syncwarp(); }
                float2 xr0 = __ldg((const float2*)(g_Xr + o0));
                float2 xr1 = __ldg((const float2*)(g_Xr + o1));
                float a0 = sigf(xr0.x + acc[0]) * hv0x;
                float a1 = sigf(xr0.y + acc[1]) * hv0y;
                float a2 = sigf(xr1.x + acc[2]) * hv1x;
                float a3 = sigf(xr1.y + acc[3]) * hv1y;
                uint32_t hi, lo;
                split2(a0, a1, hi, lo);
                __stcg((uint32_t*)(g_Rh_hi[p] + h0o), hi);
                __stcg((uint32_t*)(g_Rh_lo[p] + h0o), lo);
                split2(a2, a3, hi, lo);
                __stcg((uint32_t*)(g_Rh_hi[p] + h1o), hi);
                __stcg((uint32_t*)(g_Rh_lo[p] + h1o), lo);
            } else {
                float2 xz0 = __ldg((const float2*)(g_Xz + o0));
                float2 xz1 = __ldg((const float2*)(g_Xz + o1));
                *(float2*)(sm + RS_Z + (r0 * 8 + qn) * 4) =
                    make_float2(sigf(xz0.x + acc[0]), sigf(xz0.y + acc[1]));
                *(float2*)(sm + RS_Z + ((r0 + 8) * 8 + qn) * 4) =
                    make_float2(sigf(xz1.x + acc[2]), sigf(xz1.y + acc[3]));
            }
        }
        __syncthreads();
        if (tid == 0) red_rel_gpu(&g_cnt_rh[bid >> 4], 1u);   // Rh slice published

        // ================ phase 2: H_hat (warps 0-3) ======================
        float acch[4] = {0.f, 0.f, 0.f, 0.f};
        if (w >= 8) {
            const int j = w - 8;
            unsigned consTgt = (j < 4) ? 12u * (unsigned)t + 8u : 12u * (unsigned)t + 12u;
            prodLoad(g_Rh_hi[p], g_Rh_lo[p], j, consTgt, g_cnt_rh + j, gtgt, tok2);
        } else if (w < 4) {
            #pragma unroll 1
            for (int j = 0; j < 8; j++) {
                if (lane == 0) smemWaitGE(FULLB + j * 4, tok2);
                __syncwarp();
                mmaChunk(acch, j, whh_hi);
                __syncwarp();
                if (lane == 0) red_rel_sh(CONSB + j * 4, 1u);
            }
            if (tid == 0) red_rel_gpu(&g_p2done, 1u);   // all Rh loads witnessed done
        }
        // ---- epilogue 2 ----
        if (w < 4) {
            // WAR: h buf pn last read in phase 1 of step t-1
            if (t >= 1) { if (lane == 0) waitGE(&g_p1done, 128u * (unsigned)t); __syncwarp(); }
            size_t o0 = (size_t)t * BH + (size_t)r0 * 1024 + col;
            size_t o1 = o0 + 8 * 1024;
            size_t h0o = (size_t)r0 * 1024 + col, h1o = h0o + 8 * 1024;
            float2 xh0 = __ldg((const float2*)(g_Xh + o0));
            float2 xh1 = __ldg((const float2*)(g_Xh + o1));
            float2 z0 = *(const float2*)(sm + RS_Z + (r0 * 8 + qn) * 4);
            float2 z1 = *(const float2*)(sm + RS_Z + ((r0 + 8) * 8 + qn) * 4);
            float n0 = z0.x * hv0x + (1.f - z0.x) * tanhf(xh0.x + acch[0]);
            float n1 = z0.y * hv0y + (1.f - z0.y) * tanhf(xh0.y + acch[1]);
            float n2 = z1.x * hv1x + (1.f - z1.x) * tanhf(xh1.x + acch[2]);
            float n3 = z1.y * hv1y + (1.f - z1.y) * tanhf(xh1.y + acch[3]);
            hv0x = n0; hv0y = n1; hv1x = n2; hv1y = n3;
            *(float2*)(out + o0) = make_float2(n0, n1);
            *(float2*)(out + o1) = make_float2(n2, n3);
            uint32_t hi, lo;
            split2(n0, n1, hi, lo);
            __stcg((uint32_t*)(g_h_hi[pn] + h0o), hi);
            __stcg((uint32_t*)(g_h_lo[pn] + h0o), lo);
            split2(n2, n3, hi, lo);
            __stcg((uint32_t*)(g_h_hi[pn] + h1o), hi);
            __stcg((uint32_t*)(g_h_lo[pn] + h1o), lo);
            if (t == TT - 1) {
                size_t f0 = (size_t)TT * BH + h0o;
                *(float2*)(out + f0)            = make_float2(n0, n1);
                *(float2*)(out + f0 + 8 * 1024) = make_float2(n2, n3);
            }
        }
        __syncthreads();
        if (tid == 0) red_rel_gpu(&g_cnt_h[bid >> 4], 1u);    // h slice published
    }
}

// ---------------- launch ---------------------------------------------------
extern "C" void kernel_launch(void* const* d_in, const int* in_sizes, int n_in,
                              void* d_out, int out_size) {
    const float* X    = (const float*)d_in[0];
    const float* state= (const float*)d_in[1];
    const float* W_xr = (const float*)d_in[2];
    const float* W_hr = (const float*)d_in[3];
    const float* b_r  = (const float*)d_in[4];
    const float* W_xz = (const float*)d_in[5];
    const float* W_hz = (const float*)d_in[6];
    const float* b_z  = (const float*)d_in[7];
    const float* W_xh = (const float*)d_in[8];
    const float* W_hh = (const float*)d_in[9];
    const float* b_h  = (const float*)d_in[10];
    float* out = (float*)d_out;

    __nv_bfloat16 *xhi, *xlo, *whi, *wlo;
    cudaGetSymbolAddress((void**)&xhi, g_X_hi);
    cudaGetSymbolAddress((void**)&xlo, g_X_lo);
    cudaGetSymbolAddress((void**)&whi, g_W_hi);
    cudaGetSymbolAddress((void**)&wlo, g_W_lo);

    split_pass<<<(TT * BB * DH / 4 + 255) / 256, 256>>>(X, xhi, xlo, TT * BB * DH / 4);
    split_pass<<<(1048576 / 4 + 255) / 256, 256>>>(W_xr, whi, wlo, 1048576 / 4);
    split_pass<<<(1048576 / 4 + 255) / 256, 256>>>(W_xz, whi + 1048576, wlo + 1048576, 1048576 / 4);
    split_pass<<<(1048576 / 4 + 255) / 256, 256>>>(W_xh, whi + 2097152, wlo + 2097152, 1048576 / 4);

    cudaFuncSetAttribute(input_gemm,
                         cudaFuncAttributeMaxDynamicSharedMemorySize, IG_TOT);
    dim3 g1(4, 256, 3);
    input_gemm<<<g1, 512, IG_TOT>>>(b_r, b_z, b_h);

    cudaFuncSetAttribute(gru_recurrent,
                         cudaFuncAttributeMaxDynamicSharedMemorySize, RS_TOT);
    gru_recurrent<<<NB, 512, RS_TOT>>>(state, W_hr, W_hz, W_hh, out);
}

// round 9
// speedup vs baseline: 1.1465x; 1.1465x over previous
#include <cuda_runtime.h>
#include <cuda_bf16.h>
#include <math.h>
#include <stdint.h>

#define TT 512
#define BB 64
#define DH 1024
#define BH (BB*DH)
#define NB 128          // persistent blocks, 1/SM
#define CPB 8           // hidden columns per block

// ---------------- recurrent kernel SMEM layout (bytes) --------------------
#define RS_W    0          // 6 slabs x 16384 (WRhi,WRlo,WZhi,WZlo,WHhi,WHlo)
#define RS_A    98304      // 2 buffers x (hi 32768 + lo 32768)
#define RS_ABUF 65536
#define RS_ALOD 32768
#define RS_Z    229376     // z gate buf 64x8 f32
#define RS_TOT  231424

// ---------------- input gemm SMEM layout (bytes, per stage) ---------------
#define IG_AH   0
#define IG_AL   16384
#define IG_WH   32768
#define IG_WL   65536
#define IG_STG  98304
#define IG_TOT  196608

// ---------------- device globals ------------------------------------------
__device__ float g_Xr[(size_t)TT * BH];
__device__ float g_Xz[(size_t)TT * BH];
__device__ float g_Xh[(size_t)TT * BH];
__device__ __nv_bfloat16 g_X_hi[(size_t)TT * BB * DH];
__device__ __nv_bfloat16 g_X_lo[(size_t)TT * BB * DH];
__device__ __nv_bfloat16 g_W_hi[3u * 1024u * 1024u];
__device__ __nv_bfloat16 g_W_lo[3u * 1024u * 1024u];
__device__ float g_h_f32[BH];
__device__ __nv_bfloat16 g_h_hi[2][BH], g_h_lo[2][BH];
__device__ __nv_bfloat16 g_Rh_hi[2][BH], g_Rh_lo[2][BH];
__device__ unsigned g_cnt_h[4];     // h-producer counters, per 256-col k-chunk
__device__ unsigned g_cnt_rh[4];    // Rh-producer counters, per k-chunk
__device__ unsigned g_p1done;       // blocks done reading h (phase 1)
__device__ unsigned g_p2done;       // blocks done reading Rh (phase 2)
__device__ unsigned g_bar_count = 0;
__device__ volatile unsigned g_bar_gen = 0;

// ---------------- helpers -------------------------------------------------
__device__ __forceinline__ uint32_t smem_u32(const void* p) {
    uint32_t a;
    asm("{ .reg .u64 t; cvta.to.shared.u64 t, %1; cvt.u32.u64 %0, t; }" : "=r"(a) : "l"(p));
    return a;
}
__device__ __forceinline__ void mma16816(float* c, const uint32_t* a, const uint32_t* b) {
    asm volatile("mma.sync.aligned.m16n8k16.row.col.f32.bf16.bf16.f32 "
        "{%0,%1,%2,%3}, {%4,%5,%6,%7}, {%8,%9}, {%0,%1,%2,%3};"
        : "+f"(c[0]), "+f"(c[1]), "+f"(c[2]), "+f"(c[3])
        : "r"(a[0]), "r"(a[1]), "r"(a[2]), "r"(a[3]), "r"(b[0]), "r"(b[1]));
}
__device__ __forceinline__ void ldsm_x4(uint32_t* r, uint32_t a) {
    asm volatile("ldmatrix.sync.aligned.m8n8.x4.shared.b16 {%0,%1,%2,%3}, [%4];"
        : "=r"(r[0]), "=r"(r[1]), "=r"(r[2]), "=r"(r[3]) : "r"(a));
}
__device__ __forceinline__ void ldsm_x2t(uint32_t* r, uint32_t a) {
    asm volatile("ldmatrix.sync.aligned.m8n8.x2.trans.shared.b16 {%0,%1}, [%2];"
        : "=r"(r[0]), "=r"(r[1]) : "r"(a));
}
__device__ __forceinline__ void ldsm_x4t(uint32_t* r, uint32_t a) {
    asm volatile("ldmatrix.sync.aligned.m8n8.x4.trans.shared.b16 {%0,%1,%2,%3}, [%4];"
        : "=r"(r[0]), "=r"(r[1]), "=r"(r[2]), "=r"(r[3]) : "r"(a));
}
#define CPASYNC16(dst, src) asm volatile("cp.async.cg.shared.global [%0], [%1], 16;" :: "r"(dst), "l"(src))
#define CPCOMMIT() asm volatile("cp.async.commit_group;" ::: "memory")
#define CPWAIT1()  asm volatile("cp.async.wait_group 1;" ::: "memory")
#define CPWAIT0()  asm volatile("cp.async.wait_group 0;" ::: "memory")

__device__ __forceinline__ unsigned ld_acq_g(const unsigned* p) {
    unsigned v;
    asm volatile("ld.acquire.gpu.global.u32 %0, [%1];" : "=r"(v) : "l"(p) : "memory");
    return v;
}
__device__ __forceinline__ void waitGE(const unsigned* p, unsigned tgt) {
    while ((int)(ld_acq_g(p) - tgt) < 0) { }
}
__device__ __forceinline__ void red_rel_gpu(unsigned* p, unsigned v) {
    asm volatile("red.release.gpu.global.add.u32 [%0], %1;" :: "l"(p), "r"(v) : "memory");
}

__device__ __forceinline__ uint32_t packbf(__nv_bfloat16 x, __nv_bfloat16 y) {
    unsigned short ux = *(unsigned short*)&x, uy = *(unsigned short*)&y;
    return (uint32_t)ux | ((uint32_t)uy << 16);
}
__device__ __forceinline__ void split2(float vx, float vy, uint32_t& hi, uint32_t& lo) {
    __nv_bfloat16 hx = __float2bfloat16(vx), hy = __float2bfloat16(vy);
    __nv_bfloat16 lx = __float2bfloat16(vx - __bfloat162float(hx));
    __nv_bfloat16 ly = __float2bfloat16(vy - __bfloat162float(hy));
    hi = packbf(hx, hy); lo = packbf(lx, ly);
}
__device__ __forceinline__ float sigf(float x) { return 1.0f / (1.0f + expf(-x)); }
__device__ __forceinline__ uint32_t swz32(uint32_t s, uint32_t r) {
    return ((s & 7u) ^ (r & 7u)) | (s & 24u);
}

// ---------------- grid barrier (init only) --------------------------------
__device__ __forceinline__ void gridBarrier() {
    __syncthreads();
    if (threadIdx.x == 0) {
        __threadfence();
        unsigned g = g_bar_gen;
        if (atomicAdd(&g_bar_count, 1u) == (unsigned)(NB - 1)) {
            g_bar_count = 0;
            __threadfence();
            g_bar_gen = g + 1;
        } else {
            while (g_bar_gen == g) { }
        }
        __threadfence();
    }
    __syncthreads();
}

// ---------------- prepass: fp32 -> bf16 hi/lo split -----------------------
__global__ void __launch_bounds__(256) split_pass(
    const float* __restrict__ src, __nv_bfloat16* __restrict__ hi,
    __nv_bfloat16* __restrict__ lo, int n4)
{
    int i = blockIdx.x * 256 + threadIdx.x;
    if (i >= n4) return;
    float4 v = __ldg((const float4*)src + i);
    uint32_t h0, l0, h1, l1;
    split2(v.x, v.y, h0, l0);
    split2(v.z, v.w, h1, l1);
    ((uint2*)hi)[i] = make_uint2(h0, h1);
    ((uint2*)lo)[i] = make_uint2(l0, l1);
}

// ---------------- input projection GEMM (HMMA, cp.async pipeline) ---------
__global__ void __launch_bounds__(512, 1) input_gemm(
    const float* __restrict__ br, const float* __restrict__ bz, const float* __restrict__ bh)
{
    extern __shared__ char sm[];
    const uint32_t sb = smem_u32(sm);
    const int z = blockIdx.z;
    const float* bias = (z == 0) ? br : (z == 1) ? bz : bh;
    float* Out = (z == 0) ? g_Xr : (z == 1) ? g_Xz : g_Xh;
    const __nv_bfloat16* WHi = g_W_hi + (size_t)z * 1048576u;
    const __nv_bfloat16* WLo = g_W_lo + (size_t)z * 1048576u;

    const int tid = threadIdx.x;
    const int lane = tid & 31, w = tid >> 5;
    const int rowBase = blockIdx.y * 128;
    const int colBase = blockIdx.x * 256;
    const int mw = (w & 3) * 32;
    const int nw = (w >> 2) * 64;

    float acc[2][8][4];
    #pragma unroll
    for (int i = 0; i < 2; i++)
        #pragma unroll
        for (int j = 0; j < 8; j++)
            #pragma unroll
            for (int q = 0; q < 4; q++) acc[i][j][q] = 0.f;

    auto stage = [&](int c, uint32_t bufSm) {
        const int k0 = c * 64;
        #pragma unroll
        for (int it = 0; it < 2; it++) {
            int idx = tid + it * 512;
            int r = idx >> 3, s = idx & 7;
            uint32_t d = bufSm + IG_AH + r * 128 + ((s ^ (r & 7)) * 16);
            const __nv_bfloat16* g = g_X_hi + (size_t)(rowBase + r) * 1024 + k0 + s * 8;
            CPASYNC16(d, g);
            d = bufSm + IG_AL + r * 128 + ((s ^ (r & 7)) * 16);
            g = g_X_lo + (size_t)(rowBase + r) * 1024 + k0 + s * 8;
            CPASYNC16(d, g);
        }
        #pragma unroll
        for (int it = 0; it < 4; it++) {
            int idx = tid + it * 512;
            int k = idx >> 5, s = idx & 31;
            uint32_t d = bufSm + IG_WH + k * 512 + swz32(s, k) * 16;
            const __nv_bfloat16* g = WHi + (size_t)(k0 + k) * 1024 + colBase + s * 8;
            CPASYNC16(d, g);
            d = bufSm + IG_WL + k * 512 + swz32(s, k) * 16;
            g = WLo + (size_t)(k0 + k) * 1024 + colBase + s * 8;
            CPASYNC16(d, g);
        }
    };

    stage(0, sb + 0);
    CPCOMMIT();

    for (int c = 0; c < 16; c++) {
        const uint32_t cur = sb + (uint32_t)(c & 1) * IG_STG;
        if (c < 15) {
            stage(c + 1, sb + (uint32_t)((c + 1) & 1) * IG_STG);
            CPCOMMIT();
            CPWAIT1();
        } else {
            CPWAIT0();
        }
        __syncthreads();

        #pragma unroll
        for (int ks = 0; ks < 4; ks++) {
            uint32_t ah[2][4], al[2][4];
            #pragma unroll
            for (int i = 0; i < 2; i++) {
                int row = mw + i * 16 + (lane & 15);
                int s = ks * 2 + (lane >> 4);
                uint32_t ab = cur + row * 128 + ((s ^ (row & 7)) * 16);
                ldsm_x4(ah[i], ab + IG_AH);
                ldsm_x4(al[i], ab + IG_AL);
            }
            #pragma unroll
            for (int jp = 0; jp < 4; jp++) {
                int rrow = ks * 16 + (lane & 15);
                int sc = (nw >> 3) + jp * 2 + (lane >> 4);
                uint32_t bb = cur + rrow * 512 + swz32((uint32_t)sc, (uint32_t)rrow) * 16;
                uint32_t bh[4], bl[4];
                ldsm_x4t(bh, bb + IG_WH);
                ldsm_x4t(bl, bb + IG_WL);
                #pragma unroll
                for (int i = 0; i < 2; i++) {
                    mma16816(acc[i][jp*2+0], ah[i], &bh[0]);
                    mma16816(acc[i][jp*2+0], al[i], &bh[0]);
                    mma16816(acc[i][jp*2+0], ah[i], &bl[0]);
                    mma16816(acc[i][jp*2+1], ah[i], &bh[2]);
                    mma16816(acc[i][jp*2+1], al[i], &bh[2]);
                    mma16816(acc[i][jp*2+1], ah[i], &bl[2]);
                }
            }
        }
        __syncthreads();
    }

    const int g = lane >> 2, qn = (lane & 3) * 2;
    #pragma unroll
    for (int j = 0; j < 8; j++) {
        int col = colBase + nw + j * 8 + qn;
        float2 bv = *(const float2*)(bias + col);
        #pragma unroll
        for (int i = 0; i < 2; i++) {
            int r0 = rowBase + mw + i * 16 + g;
            *(float2*)(Out + (size_t)r0 * 1024 + col) =
                make_float2(acc[i][j][0] + bv.x, acc[i][j][1] + bv.y);
            *(float2*)(Out + (size_t)(r0 + 8) * 1024 + col) =
                make_float2(acc[i][j][2] + bv.x, acc[i][j][3] + bv.y);
        }
    }
}

// ---------------- recurrent kernel (persistent, dataflow-synced) ----------
// 128 blocks x 512 threads. Warps 0-7 compute; warps 8-15 poll+stream chunks.
// Chunk order is staggered per block: start at own publisher group's chunk.
__global__ void __launch_bounds__(512, 1) gru_recurrent(
    const float* __restrict__ state,
    const float* __restrict__ Whr, const float* __restrict__ Whz, const float* __restrict__ Whh,
    float* __restrict__ out)
{
    extern __shared__ char sm[];
    const uint32_t sb = smem_u32(sm);
    const int tid = threadIdx.x;
    const int lane = tid & 31, w = tid >> 5;
    const int bid = blockIdx.x;
    const int cB  = bid * CPB;
    const int mychunk = bid >> 5;      // 4 chunks, 32 publishers each
    const int cstart  = mychunk;       // staggered start chunk

    // ---- reset dataflow counters (block 0) ----
    if (bid == 0 && tid == 0) {
        #pragma unroll
        for (int c = 0; c < 4; c++) { g_cnt_h[c] = 32u; g_cnt_rh[c] = 0u; }
        g_p1done = 0u; g_p2done = 0u;
    }

    // ---- persistent W slabs: [k][8n] rows of 16B, hi/lo bf16 ----
    {
        const float* Wm[3] = { Whr, Whz, Whh };
        for (int idx = tid; idx < 8192; idx += 512) {
            int k = idx >> 3, n = idx & 7;
            #pragma unroll
            for (int m = 0; m < 3; m++) {
                float v = Wm[m][(size_t)k * 1024 + cB + n];
                __nv_bfloat16 h = __float2bfloat16(v);
                __nv_bfloat16 l = __float2bfloat16(v - __bfloat162float(h));
                *(__nv_bfloat16*)(sm + RS_W + (2*m)   * 16384 + k * 16 + n * 2) = h;
                *(__nv_bfloat16*)(sm + RS_W + (2*m+1) * 16384 + k * 16 + n * 2) = l;
            }
        }
    }
    // ---- init h (buffer 0) ----
    if (tid < 512) {
        int r = tid >> 3, n = tid & 7;
        size_t gi = (size_t)r * 1024 + cB + n;
        float v = state[gi];
        g_h_f32[gi] = v;
        __nv_bfloat16 h = __float2bfloat16(v);
        __nv_bfloat16 l = __float2bfloat16(v - __bfloat162float(h));
        g_h_hi[0][gi] = h; g_h_lo[0][gi] = l;
    }
    gridBarrier();   // publishes resets + weights + h0; the ONLY grid barrier

    const int m0  = (w & 3) * 16;
    const bool isR = (w < 4);
    const int g   = lane >> 2, qn = (lane & 3) * 2;
    const int r0  = m0 + g;
    const int col = cB + qn;
    const uint32_t wsel_hi = sb + RS_W + (isR ? 0 : 2) * 16384;
    const uint32_t whh_hi  = sb + RS_W + 4 * 16384;
    const int ptid = tid - 256;

    auto loadChunk = [&](const __nv_bfloat16* hi, const __nv_bfloat16* lo, int c, int b) {
        char* buf = sm + RS_A + b * RS_ABUF;
        const int kbase = c * 256;
        #pragma unroll
        for (int it = 0; it < 8; it++) {
            int idx = ptid + it * 256;
            int r = idx >> 5, s = idx & 31;
            uint32_t off = (uint32_t)r * 512 + swz32((uint32_t)s, (uint32_t)r) * 16;
            size_t go = (size_t)r * 1024 + kbase + s * 8;
            *(uint4*)(buf + off)           = __ldcg((const uint4*)(hi + go));
            *(uint4*)(buf + RS_ALOD + off) = __ldcg((const uint4*)(lo + go));
        }
    };
    // poll chunk-ready, then load (producer warps 8-15, 256 threads)
    auto pollLoad = [&](const __nv_bfloat16* hi, const __nv_bfloat16* lo, int c, int b,
                        const unsigned* cnt, unsigned tgt) {
        if (w == 8) waitGE(cnt + c, tgt);
        asm volatile("bar.sync 1, 256;" ::: "memory");
        loadChunk(hi, lo, c, b);
    };
    // consume chunk with k-offset of chunk id c from buffer b
    auto mmaChunk = [&](float* acc, int b, uint32_t wHi, int c) {
        const uint32_t abase = sb + RS_A + (uint32_t)b * RS_ABUF;
        const int arow = m0 + (lane & 15);
        #pragma unroll
        for (int ks2 = 0; ks2 < 8; ks2++) {
            uint32_t bh[4], bl[4];
            uint32_t baddr = wHi + (uint32_t)(c * 256 + ks2 * 32 + lane) * 16;
            ldsm_x4t(bh, baddr);
            ldsm_x4t(bl, baddr + 16384);
            uint32_t ah0[4], al0[4], ah1[4], al1[4];
            int s0 = (ks2 * 2) * 2 + (lane >> 4);
            int s1 = s0 + 2;
            uint32_t a0 = abase + (uint32_t)arow * 512 + swz32((uint32_t)s0, (uint32_t)arow) * 16;
            uint32_t a1 = abase + (uint32_t)arow * 512 + swz32((uint32_t)s1, (uint32_t)arow) * 16;
            ldsm_x4(ah0, a0); ldsm_x4(al0, a0 + RS_ALOD);
            ldsm_x4(ah1, a1); ldsm_x4(al1, a1 + RS_ALOD);
            mma16816(acc, ah0, &bh[0]);
            mma16816(acc, al0, &bh[0]);
            mma16816(acc, ah0, &bl[0]);
            mma16816(acc, ah1, &bh[2]);
            mma16816(acc, al1, &bh[2]);
            mma16816(acc, ah1, &bl[2]);
        }
    };

    for (int t = 0; t < TT; t++) {
        const unsigned tgt = 32u * (unsigned)(t + 1);
        const int p  = t & 1;          // read parity
        const int pn = (t + 1) & 1;    // write parity for h
        const size_t xoffB = (size_t)t * BH + (size_t)r0 * 1024 + col;

        // ================ phase 1: R (warps 0-3) / Z (warps 4-7) ==========
        float acc[4] = {0.f, 0.f, 0.f, 0.f};
        const __nv_bfloat16* Hhi = g_h_hi[p];
        const __nv_bfloat16* Hlo = g_h_lo[p];
        // prefetch epilogue-1 X inputs (hidden under the MMA loop)
        float2 x1a, x1b;
        if (w < 8) {
            const float* Xsrc = isR ? g_Xr : g_Xz;
            x1a = __ldg((const float2*)(Xsrc + xoffB));
            x1b = __ldg((const float2*)(Xsrc + xoffB + 8 * 1024));
        }
        if (w >= 8) pollLoad(Hhi, Hlo, cstart, 0, g_cnt_h, tgt);
        for (int c = 0; c < 4; c++) {
            __syncthreads();
            if (w < 8)      mmaChunk(acc, c & 1, wsel_hi, (cstart + c) & 3);
            else if (c < 3) pollLoad(Hhi, Hlo, (cstart + c + 1) & 3, (c + 1) & 1, g_cnt_h, tgt);
            else if (tid == 256) red_rel_gpu(&g_p1done, 1u);   // all h reads done
        }
        // ---- epilogue 1 ----
        if (w < 8) {
            size_t h0o = (size_t)r0 * 1024 + col, h1o = h0o + 8 * 1024;
            if (isR) {
                // WAR: Rh buf p last read in phase 2 of step t-2
                if (t >= 2) waitGE(&g_p2done, 128u * (unsigned)(t - 1));
                float2 h0 = *(const float2*)(g_h_f32 + h0o);
                float2 h1 = *(const float2*)(g_h_f32 + h1o);
                float a0 = sigf(x1a.x + acc[0]) * h0.x;
                float a1 = sigf(x1a.y + acc[1]) * h0.y;
                float a2 = sigf(x1b.x + acc[2]) * h1.x;
                float a3 = sigf(x1b.y + acc[3]) * h1.y;
                uint32_t hi, lo;
                split2(a0, a1, hi, lo);
                __stcg((uint32_t*)(g_Rh_hi[p] + h0o), hi);
                __stcg((uint32_t*)(g_Rh_lo[p] + h0o), lo);
                split2(a2, a3, hi, lo);
                __stcg((uint32_t*)(g_Rh_hi[p] + h1o), hi);
                __stcg((uint32_t*)(g_Rh_lo[p] + h1o), lo);
                __threadfence();
            } else {
                *(float2*)(sm + RS_Z + (r0 * 8 + qn) * 4) =
                    make_float2(sigf(x1a.x + acc[0]), sigf(x1a.y + acc[1]));
                *(float2*)(sm + RS_Z + ((r0 + 8) * 8 + qn) * 4) =
                    make_float2(sigf(x1b.x + acc[2]), sigf(x1b.y + acc[3]));
            }
        }
        __syncthreads();
        if (tid == 0) red_rel_gpu(&g_cnt_rh[mychunk], 1u);    // Rh slice published

        // ================ phase 2: H_hat (warps 0-3) ======================
        float acch[4] = {0.f, 0.f, 0.f, 0.f};
        const __nv_bfloat16* Rhi = g_Rh_hi[p];
        const __nv_bfloat16* Rlo = g_Rh_lo[p];
        float2 x2a, x2b;
        if (w < 4) {
            x2a = __ldg((const float2*)(g_Xh + xoffB));
            x2b = __ldg((const float2*)(g_Xh + xoffB + 8 * 1024));
        }
        if (w >= 8) pollLoad(Rhi, Rlo, cstart, 0, g_cnt_rh, tgt);
        for (int c = 0; c < 4; c++) {
            __syncthreads();
            if (w < 4)      mmaChunk(acch, c & 1, whh_hi, (cstart + c) & 3);
            else if (w >= 8) {
                if (c < 3)  pollLoad(Rhi, Rlo, (cstart + c + 1) & 3, (c + 1) & 1, g_cnt_rh, tgt);
                else if (tid == 256) red_rel_gpu(&g_p2done, 1u);  // all Rh reads done
            }
        }
        // ---- epilogue 2 ----
        if (w < 4) {
            // WAR: h buf pn last read in phase 1 of step t-1
            if (t >= 1) waitGE(&g_p1done, 128u * (unsigned)t);
            size_t o0 = xoffB, o1 = xoffB + 8 * 1024;
            size_t h0o = (size_t)r0 * 1024 + col, h1o = h0o + 8 * 1024;
            float2 z0 = *(const float2*)(sm + RS_Z + (r0 * 8 + qn) * 4);
            float2 z1 = *(const float2*)(sm + RS_Z + ((r0 + 8) * 8 + qn) * 4);
            float2 h0 = *(const float2*)(g_h_f32 + h0o);
            float2 h1 = *(const float2*)(g_h_f32 + h1o);
            float n0 = z0.x * h0.x + (1.f - z0.x) * tanhf(x2a.x + acch[0]);
            float n1 = z0.y * h0.y + (1.f - z0.y) * tanhf(x2a.y + acch[1]);
            float n2 = z1.x * h1.x + (1.f - z1.x) * tanhf(x2b.x + acch[2]);
            float n3 = z1.y * h1.y + (1.f - z1.y) * tanhf(x2b.y + acch[3]);
            *(float2*)(out + o0) = make_float2(n0, n1);
            *(float2*)(out + o1) = make_float2(n2, n3);
            *(float2*)(g_h_f32 + h0o) = make_float2(n0, n1);
            *(float2*)(g_h_f32 + h1o) = make_float2(n2, n3);
            uint32_t hi, lo;
            split2(n0, n1, hi, lo);
            __stcg((uint32_t*)(g_h_hi[pn] + h0o), hi);
            __stcg((uint32_t*)(g_h_lo[pn] + h0o), lo);
            split2(n2, n3, hi, lo);
            __stcg((uint32_t*)(g_h_hi[pn] + h1o), hi);
            __stcg((uint32_t*)(g_h_lo[pn] + h1o), lo);
            if (t == TT - 1) {
                size_t f0 = (size_t)TT * BH + h0o;
                *(float2*)(out + f0)            = make_float2(n0, n1);
                *(float2*)(out + f0 + 8 * 1024) = make_float2(n2, n3);
            }
            __threadfence();
        }
        __syncthreads();
        if (tid == 0) red_rel_gpu(&g_cnt_h[mychunk], 1u);     // h slice published
    }
}

// ---------------- launch ---------------------------------------------------
extern "C" void kernel_launch(void* const* d_in, const int* in_sizes, int n_in,
                              void* d_out, int out_size) {
    const float* X    = (const float*)d_in[0];
    const float* state= (const float*)d_in[1];
    const float* W_xr = (const float*)d_in[2];
    const float* W_hr = (const float*)d_in[3];
    const float* b_r  = (const float*)d_in[4];
    const float* W_xz = (const float*)d_in[5];
    const float* W_hz = (const float*)d_in[6];
    const float* b_z  = (const float*)d_in[7];
    const float* W_xh = (const float*)d_in[8];
    const float* W_hh = (const float*)d_in[9];
    const float* b_h  = (const float*)d_in[10];
    float* out = (float*)d_out;

    __nv_bfloat16 *xhi, *xlo, *whi, *wlo;
    cudaGetSymbolAddress((void**)&xhi, g_X_hi);
    cudaGetSymbolAddress((void**)&xlo, g_X_lo);
    cudaGetSymbolAddress((void**)&whi, g_W_hi);
    cudaGetSymbolAddress((void**)&wlo, g_W_lo);

    split_pass<<<(TT * BB * DH / 4 + 255) / 256, 256>>>(X, xhi, xlo, TT * BB * DH / 4);
    split_pass<<<(1048576 / 4 + 255) / 256, 256>>>(W_xr, whi, wlo, 1048576 / 4);
    split_pass<<<(1048576 / 4 + 255) / 256, 256>>>(W_xz, whi + 1048576, wlo + 1048576, 1048576 / 4);
    split_pass<<<(1048576 / 4 + 255) / 256, 256>>>(W_xh, whi + 2097152, wlo + 2097152, 1048576 / 4);

    cudaFuncSetAttribute(input_gemm,
                         cudaFuncAttributeMaxDynamicSharedMemorySize, IG_TOT);
    dim3 g1(4, 256, 3);
    input_gemm<<<g1, 512, IG_TOT>>>(b_r, b_z, b_h);

    cudaFuncSetAttribute(gru_recurrent,
                         cudaFuncAttributeMaxDynamicSharedMemorySize, RS_TOT);
    gru_recurrent<<<NB, 512, RS_TOT>>>(state, W_hr, W_hz, W_hh, out);
}

// round 10
// speedup vs baseline: 1.5615x; 1.3619x over previous
#include <cuda_runtime.h>
#include <cuda_bf16.h>
#include <cuda_fp16.h>
#include <math.h>
#include <stdint.h>

#define TT 512
#define BB 64
#define DH 1024
#define BH (BB*DH)
#define NB 128          // persistent blocks, 1/SM
#define CPB 8           // hidden columns per block

// ---------------- recurrent kernel SMEM layout (bytes) --------------------
// W slabs: 6 x 16384 (WRhi,WRlo,WZhi,WZlo,WHhi,WHlo) fp16
#define RS_W    0
#define RS_A    98304      // 2 buffers x 32768 (fp16 h chunk: 64 rows x 512B)
#define RS_ABUF 32768
#define RS_Z    163840     // z gate buf 64x8 f32
#define RS_TOT  165888

// ---------------- input gemm SMEM layout (bytes, per stage) ---------------
#define IG_AH   0
#define IG_AL   16384
#define IG_WH   32768
#define IG_WL   65536
#define IG_STG  98304
#define IG_TOT  196608

// ---------------- device globals ------------------------------------------
__device__ float g_Xr[(size_t)TT * BH];
__device__ float g_Xz[(size_t)TT * BH];
__device__ float g_Xh[(size_t)TT * BH];
__device__ __nv_bfloat16 g_X_hi[(size_t)TT * BB * DH];
__device__ __nv_bfloat16 g_X_lo[(size_t)TT * BB * DH];
__device__ __nv_bfloat16 g_W_hi[3u * 1024u * 1024u];
__device__ __nv_bfloat16 g_W_lo[3u * 1024u * 1024u];
__device__ float g_h_f32[BH];
__device__ __half g_h16[4][BH];      // 4-deep h exchange buffers (fp16)
__device__ __half g_Rh16[4][BH];     // 4-deep Rh exchange buffers (fp16)
__device__ unsigned g_cnt_h[4];      // h-producer counters, per 256-col k-chunk
__device__ unsigned g_cnt_rh[4];     // Rh-producer counters, per k-chunk
__device__ unsigned g_p1done;        // blocks done reading h (phase 1)
__device__ unsigned g_p2done;        // blocks done reading Rh (phase 2)
__device__ unsigned g_bar_count = 0;
__device__ volatile unsigned g_bar_gen = 0;

// ---------------- helpers -------------------------------------------------
__device__ __forceinline__ uint32_t smem_u32(const void* p) {
    uint32_t a;
    asm("{ .reg .u64 t; cvta.to.shared.u64 t, %1; cvt.u32.u64 %0, t; }" : "=r"(a) : "l"(p));
    return a;
}
__device__ __forceinline__ void mma16816(float* c, const uint32_t* a, const uint32_t* b) {
    asm volatile("mma.sync.aligned.m16n8k16.row.col.f32.bf16.bf16.f32 "
        "{%0,%1,%2,%3}, {%4,%5,%6,%7}, {%8,%9}, {%0,%1,%2,%3};"
        : "+f"(c[0]), "+f"(c[1]), "+f"(c[2]), "+f"(c[3])
        : "r"(a[0]), "r"(a[1]), "r"(a[2]), "r"(a[3]), "r"(b[0]), "r"(b[1]));
}
__device__ __forceinline__ void mma16816h(float* c, const uint32_t* a, const uint32_t* b) {
    asm volatile("mma.sync.aligned.m16n8k16.row.col.f32.f16.f16.f32 "
        "{%0,%1,%2,%3}, {%4,%5,%6,%7}, {%8,%9}, {%0,%1,%2,%3};"
        : "+f"(c[0]), "+f"(c[1]), "+f"(c[2]), "+f"(c[3])
        : "r"(a[0]), "r"(a[1]), "r"(a[2]), "r"(a[3]), "r"(b[0]), "r"(b[1]));
}
__device__ __forceinline__ void ldsm_x4(uint32_t* r, uint32_t a) {
    asm volatile("ldmatrix.sync.aligned.m8n8.x4.shared.b16 {%0,%1,%2,%3}, [%4];"
        : "=r"(r[0]), "=r"(r[1]), "=r"(r[2]), "=r"(r[3]) : "r"(a));
}
__device__ __forceinline__ void ldsm_x4t(uint32_t* r, uint32_t a) {
    asm volatile("ldmatrix.sync.aligned.m8n8.x4.trans.shared.b16 {%0,%1,%2,%3}, [%4];"
        : "=r"(r[0]), "=r"(r[1]), "=r"(r[2]), "=r"(r[3]) : "r"(a));
}
#define CPASYNC16(dst, src) asm volatile("cp.async.cg.shared.global [%0], [%1], 16;" :: "r"(dst), "l"(src))
#define CPCOMMIT() asm volatile("cp.async.commit_group;" ::: "memory")
#define CPWAIT1()  asm volatile("cp.async.wait_group 1;" ::: "memory")
#define CPWAIT0()  asm volatile("cp.async.wait_group 0;" ::: "memory")

__device__ __forceinline__ unsigned ld_acq_g(const unsigned* p) {
    unsigned v;
    asm volatile("ld.acquire.gpu.global.u32 %0, [%1];" : "=r"(v) : "l"(p) : "memory");
    return v;
}
__device__ __forceinline__ void waitGE(const unsigned* p, unsigned tgt) {
    while ((int)(ld_acq_g(p) - tgt) < 0) { }
}
__device__ __forceinline__ void red_rel_gpu(unsigned* p, unsigned v) {
    asm volatile("red.release.gpu.global.add.u32 [%0], %1;" :: "l"(p), "r"(v) : "memory");
}

__device__ __forceinline__ uint32_t packbf(__nv_bfloat16 x, __nv_bfloat16 y) {
    unsigned short ux = *(unsigned short*)&x, uy = *(unsigned short*)&y;
    return (uint32_t)ux | ((uint32_t)uy << 16);
}
__device__ __forceinline__ void split2(float vx, float vy, uint32_t& hi, uint32_t& lo) {
    __nv_bfloat16 hx = __float2bfloat16(vx), hy = __float2bfloat16(vy);
    __nv_bfloat16 lx = __float2bfloat16(vx - __bfloat162float(hx));
    __nv_bfloat16 ly = __float2bfloat16(vy - __bfloat162float(hy));
    hi = packbf(hx, hy); lo = packbf(lx, ly);
}
__device__ __forceinline__ uint32_t packh(float x, float y) {
    __half2 hh = __floats2half2_rn(x, y);
    return *(uint32_t*)&hh;
}
__device__ __forceinline__ float sigf(float x) { return 1.0f / (1.0f + expf(-x)); }
__device__ __forceinline__ uint32_t swz32(uint32_t s, uint32_t r) {
    return ((s & 7u) ^ (r & 7u)) | (s & 24u);
}

// ---------------- grid barrier (init only) --------------------------------
__device__ __forceinline__ void gridBarrier() {
    __syncthreads();
    if (threadIdx.x == 0) {
        __threadfence();
        unsigned g = g_bar_gen;
        if (atomicAdd(&g_bar_count, 1u) == (unsigned)(NB - 1)) {
            g_bar_count = 0;
            __threadfence();
            g_bar_gen = g + 1;
        } else {
            while (g_bar_gen == g) { }
        }
        __threadfence();
    }
    __syncthreads();
}

// ---------------- prepass: fp32 -> bf16 hi/lo split -----------------------
__global__ void __launch_bounds__(256) split_pass(
    const float* __restrict__ src, __nv_bfloat16* __restrict__ hi,
    __nv_bfloat16* __restrict__ lo, int n4)
{
    int i = blockIdx.x * 256 + threadIdx.x;
    if (i >= n4) return;
    float4 v = __ldg((const float4*)src + i);
    uint32_t h0, l0, h1, l1;
    split2(v.x, v.y, h0, l0);
    split2(v.z, v.w, h1, l1);
    ((uint2*)hi)[i] = make_uint2(h0, h1);
    ((uint2*)lo)[i] = make_uint2(l0, l1);
}

// ---------------- input projection GEMM (HMMA, cp.async pipeline) ---------
__global__ void __launch_bounds__(512, 1) input_gemm(
    const float* __restrict__ br, const float* __restrict__ bz, const float* __restrict__ bh)
{
    extern __shared__ char sm[];
    const uint32_t sb = smem_u32(sm);
    const int z = blockIdx.z;
    const float* bias = (z == 0) ? br : (z == 1) ? bz : bh;
    float* Out = (z == 0) ? g_Xr : (z == 1) ? g_Xz : g_Xh;
    const __nv_bfloat16* WHi = g_W_hi + (size_t)z * 1048576u;
    const __nv_bfloat16* WLo = g_W_lo + (size_t)z * 1048576u;

    const int tid = threadIdx.x;
    const int lane = tid & 31, w = tid >> 5;
    const int rowBase = blockIdx.y * 128;
    const int colBase = blockIdx.x * 256;
    const int mw = (w & 3) * 32;
    const int nw = (w >> 2) * 64;

    float acc[2][8][4];
    #pragma unroll
    for (int i = 0; i < 2; i++)
        #pragma unroll
        for (int j = 0; j < 8; j++)
            #pragma unroll
            for (int q = 0; q < 4; q++) acc[i][j][q] = 0.f;

    auto stage = [&](int c, uint32_t bufSm) {
        const int k0 = c * 64;
        #pragma unroll
        for (int it = 0; it < 2; it++) {
            int idx = tid + it * 512;
            int r = idx >> 3, s = idx & 7;
            uint32_t d = bufSm + IG_AH + r * 128 + ((s ^ (r & 7)) * 16);
            const __nv_bfloat16* g = g_X_hi + (size_t)(rowBase + r) * 1024 + k0 + s * 8;
            CPASYNC16(d, g);
            d = bufSm + IG_AL + r * 128 + ((s ^ (r & 7)) * 16);
            g = g_X_lo + (size_t)(rowBase + r) * 1024 + k0 + s * 8;
            CPASYNC16(d, g);
        }
        #pragma unroll
        for (int it = 0; it < 4; it++) {
            int idx = tid + it * 512;
            int k = idx >> 5, s = idx & 31;
            uint32_t d = bufSm + IG_WH + k * 512 + swz32(s, k) * 16;
            const __nv_bfloat16* g = WHi + (size_t)(k0 + k) * 1024 + colBase + s * 8;
            CPASYNC16(d, g);
            d = bufSm + IG_WL + k * 512 + swz32(s, k) * 16;
            g = WLo + (size_t)(k0 + k) * 1024 + colBase + s * 8;
            CPASYNC16(d, g);
        }
    };

    stage(0, sb + 0);
    CPCOMMIT();

    for (int c = 0; c < 16; c++) {
        const uint32_t cur = sb + (uint32_t)(c & 1) * IG_STG;
        if (c < 15) {
            stage(c + 1, sb + (uint32_t)((c + 1) & 1) * IG_STG);
            CPCOMMIT();
            CPWAIT1();
        } else {
            CPWAIT0();
        }
        __syncthreads();

        #pragma unroll
        for (int ks = 0; ks < 4; ks++) {
            uint32_t ah[2][4], al[2][4];
            #pragma unroll
            for (int i = 0; i < 2; i++) {
                int row = mw + i * 16 + (lane & 15);
                int s = ks * 2 + (lane >> 4);
                uint32_t ab = cur + row * 128 + ((s ^ (row & 7)) * 16);
                ldsm_x4(ah[i], ab + IG_AH);
                ldsm_x4(al[i], ab + IG_AL);
            }
            #pragma unroll
            for (int jp = 0; jp < 4; jp++) {
                int rrow = ks * 16 + (lane & 15);
                int sc = (nw >> 3) + jp * 2 + (lane >> 4);
                uint32_t bb = cur + rrow * 512 + swz32((uint32_t)sc, (uint32_t)rrow) * 16;
                uint32_t bh[4], bl[4];
                ldsm_x4t(bh, bb + IG_WH);
                ldsm_x4t(bl, bb + IG_WL);
                #pragma unroll
                for (int i = 0; i < 2; i++) {
                    mma16816(acc[i][jp*2+0], ah[i], &bh[0]);
                    mma16816(acc[i][jp*2+0], al[i], &bh[0]);
                    mma16816(acc[i][jp*2+0], ah[i], &bl[0]);
                    mma16816(acc[i][jp*2+1], ah[i], &bh[2]);
                    mma16816(acc[i][jp*2+1], al[i], &bh[2]);
                    mma16816(acc[i][jp*2+1], ah[i], &bl[2]);
                }
            }
        }
        __syncthreads();
    }

    const int g = lane >> 2, qn = (lane & 3) * 2;
    #pragma unroll
    for (int j = 0; j < 8; j++) {
        int col = colBase + nw + j * 8 + qn;
        float2 bv = *(const float2*)(bias + col);
        #pragma unroll
        for (int i = 0; i < 2; i++) {
            int r0 = rowBase + mw + i * 16 + g;
            *(float2*)(Out + (size_t)r0 * 1024 + col) =
                make_float2(acc[i][j][0] + bv.x, acc[i][j][1] + bv.y);
            *(float2*)(Out + (size_t)(r0 + 8) * 1024 + col) =
                make_float2(acc[i][j][2] + bv.x, acc[i][j][3] + bv.y);
        }
    }
}

// ---------------- recurrent kernel (persistent, dataflow-synced, fp16) ----
// 128 blocks x 512 threads. Warps 0-7 compute; warps 8-15 poll+stream chunks.
// h / Rh cross blocks as single fp16; W held in SMEM as fp16 hi+lo (2-term).
__global__ void __launch_bounds__(512, 1) gru_recurrent(
    const float* __restrict__ state,
    const float* __restrict__ Whr, const float* __restrict__ Whz, const float* __restrict__ Whh,
    float* __restrict__ out)
{
    extern __shared__ char sm[];
    const uint32_t sb = smem_u32(sm);
    const int tid = threadIdx.x;
    const int lane = tid & 31, w = tid >> 5;
    const int bid = blockIdx.x;
    const int cB  = bid * CPB;
    const int mychunk = bid >> 5;      // 4 chunks, 32 publishers each
    const int cstart  = mychunk;       // staggered start chunk

    // ---- reset dataflow counters (block 0) ----
    if (bid == 0 && tid == 0) {
        #pragma unroll
        for (int c = 0; c < 4; c++) { g_cnt_h[c] = 32u; g_cnt_rh[c] = 0u; }
        g_p1done = 0u; g_p2done = 0u;
    }

    // ---- persistent W slabs: [k][8n] rows of 16B, fp16 hi/lo ----
    {
        const float* Wm[3] = { Whr, Whz, Whh };
        for (int idx = tid; idx < 8192; idx += 512) {
            int k = idx >> 3, n = idx & 7;
            #pragma unroll
            for (int m = 0; m < 3; m++) {
                float v = Wm[m][(size_t)k * 1024 + cB + n];
                __half h = __float2half_rn(v);
                __half l = __float2half_rn(v - __half2float(h));
                *(__half*)(sm + RS_W + (2*m)   * 16384 + k * 16 + n * 2) = h;
                *(__half*)(sm + RS_W + (2*m+1) * 16384 + k * 16 + n * 2) = l;
            }
        }
    }
    // ---- init h (buffer 0) ----
    if (tid < 512) {
        int r = tid >> 3, n = tid & 7;
        size_t gi = (size_t)r * 1024 + cB + n;
        float v = state[gi];
        g_h_f32[gi] = v;
        g_h16[0][gi] = __float2half_rn(v);
    }
    gridBarrier();   // publishes resets + weights + h0; the ONLY grid barrier

    const int m0  = (w & 3) * 16;
    const bool isR = (w < 4);
    const int g   = lane >> 2, qn = (lane & 3) * 2;
    const int r0  = m0 + g;
    const int col = cB + qn;
    const uint32_t wsel_hi = sb + RS_W + (isR ? 0 : 2) * 16384;
    const uint32_t whh_hi  = sb + RS_W + 4 * 16384;
    const int ptid = tid - 256;

    auto loadChunk = [&](const __half* src, int c, int b) {
        char* buf = sm + RS_A + b * RS_ABUF;
        const int kbase = c * 256;
        #pragma unroll
        for (int it = 0; it < 8; it++) {
            int idx = ptid + it * 256;       // 0..2047 (64 rows x 32 segs)
            int r = idx >> 5, s = idx & 31;
            uint32_t off = (uint32_t)r * 512 + swz32((uint32_t)s, (uint32_t)r) * 16;
            size_t go = (size_t)r * 1024 + kbase + s * 8;
            *(uint4*)(buf + off) = __ldcg((const uint4*)(src + go));
        }
    };
    // poll chunk-ready, then load (producer warps 8-15, 256 threads)
    auto pollLoad = [&](const __half* src, int c, int b,
                        const unsigned* cnt, unsigned tgt) {
        if (w == 8) waitGE(cnt + c, tgt);
        asm volatile("bar.sync 1, 256;" ::: "memory");
        loadChunk(src, c, b);
    };
    // consume chunk with k-offset of chunk id c from buffer b (2-term fp16)
    auto mmaChunk = [&](float* acc, int b, uint32_t wHi, int c) {
        const uint32_t abase = sb + RS_A + (uint32_t)b * RS_ABUF;
        const int arow = m0 + (lane & 15);
        #pragma unroll
        for (int ks2 = 0; ks2 < 8; ks2++) {
            uint32_t bh[4], bl[4];
            uint32_t baddr = wHi + (uint32_t)(c * 256 + ks2 * 32 + lane) * 16;
            ldsm_x4t(bh, baddr);
            ldsm_x4t(bl, baddr + 16384);
            int s0 = ks2 * 4 + (lane >> 4);
            int s1 = s0 + 2;
            uint32_t a0 = abase + (uint32_t)arow * 512 + swz32((uint32_t)s0, (uint32_t)arow) * 16;
            uint32_t a1 = abase + (uint32_t)arow * 512 + swz32((uint32_t)s1, (uint32_t)arow) * 16;
            uint32_t ah0[4], ah1[4];
            ldsm_x4(ah0, a0);
            ldsm_x4(ah1, a1);
            mma16816h(acc, ah0, &bh[0]);
            mma16816h(acc, ah0, &bl[0]);
            mma16816h(acc, ah1, &bh[2]);
            mma16816h(acc, ah1, &bl[2]);
        }
    };

    for (int t = 0; t < TT; t++) {
        const unsigned tgt = 32u * (unsigned)(t + 1);
        const int p  = t & 3;          // read buffer (4-deep)
        const int pn = (t + 1) & 3;    // write buffer for h
        const size_t xoffB = (size_t)t * BH + (size_t)r0 * 1024 + col;

        // ================ phase 1: R (warps 0-3) / Z (warps 4-7) ==========
        float acc[4] = {0.f, 0.f, 0.f, 0.f};
        const __half* Hsrc = g_h16[p];
        // prefetch epilogue-1 X inputs (hidden under the MMA loop)
        float2 x1a, x1b;
        if (w < 8) {
            const float* Xsrc = isR ? g_Xr : g_Xz;
            x1a = __ldg((const float2*)(Xsrc + xoffB));
            x1b = __ldg((const float2*)(Xsrc + xoffB + 8 * 1024));
        }
        if (w >= 8) pollLoad(Hsrc, cstart, 0, g_cnt_h, tgt);
        for (int c = 0; c < 4; c++) {
            __syncthreads();
            if (w < 8)      mmaChunk(acc, c & 1, wsel_hi, (cstart + c) & 3);
            else if (c < 3) pollLoad(Hsrc, (cstart + c + 1) & 3, (c + 1) & 1, g_cnt_h, tgt);
            else if (tid == 256) red_rel_gpu(&g_p1done, 1u);   // all h reads done
        }
        // ---- epilogue 1 ----
        if (w < 8) {
            size_t h0o = (size_t)r0 * 1024 + col, h1o = h0o + 8 * 1024;
            if (isR) {
                // WAR: Rh buf p last read in phase 2 of step t-4
                if (t >= 4) waitGE(&g_p2done, 128u * (unsigned)(t - 3));
                float2 h0 = *(const float2*)(g_h_f32 + h0o);
                float2 h1 = *(const float2*)(g_h_f32 + h1o);
                float a0 = sigf(x1a.x + acc[0]) * h0.x;
                float a1 = sigf(x1a.y + acc[1]) * h0.y;
                float a2 = sigf(x1b.x + acc[2]) * h1.x;
                float a3 = sigf(x1b.y + acc[3]) * h1.y;
                __stcg((uint32_t*)(g_Rh16[p] + h0o), packh(a0, a1));
                __stcg((uint32_t*)(g_Rh16[p] + h1o), packh(a2, a3));
                __threadfence();
            } else {
                *(float2*)(sm + RS_Z + (r0 * 8 + qn) * 4) =
                    make_float2(sigf(x1a.x + acc[0]), sigf(x1a.y + acc[1]));
                *(float2*)(sm + RS_Z + ((r0 + 8) * 8 + qn) * 4) =
                    make_float2(sigf(x1b.x + acc[2]), sigf(x1b.y + acc[3]));
            }
        }
        __syncthreads();
        if (tid == 0) red_rel_gpu(&g_cnt_rh[mychunk], 1u);    // Rh slice published

        // ================ phase 2: H_hat (warps 0-3) ======================
        float acch[4] = {0.f, 0.f, 0.f, 0.f};
        const __half* Rsrc = g_Rh16[p];
        float2 x2a, x2b;
        if (w < 4) {
            x2a = __ldg((const float2*)(g_Xh + xoffB));
            x2b = __ldg((const float2*)(g_Xh + xoffB + 8 * 1024));
        }
        if (w >= 8) pollLoad(Rsrc, cstart, 0, g_cnt_rh, tgt);
        for (int c = 0; c < 4; c++) {
            __syncthreads();
            if (w < 4)      mmaChunk(acch, c & 1, whh_hi, (cstart + c) & 3);
            else if (w >= 8) {
                if (c < 3)  pollLoad(Rsrc, (cstart + c + 1) & 3, (c + 1) & 1, g_cnt_rh, tgt);
                else if (tid == 256) red_rel_gpu(&g_p2done, 1u);  // all Rh reads done
            }
        }
        // ---- epilogue 2 ----
        if (w < 4) {
            // WAR: h buf pn last written step t-4, read in phase 1 of step t-3
            if (t >= 3) waitGE(&g_p1done, 128u * (unsigned)(t - 2));
            size_t o0 = xoffB, o1 = xoffB + 8 * 1024;
            size_t h0o = (size_t)r0 * 1024 + col, h1o = h0o + 8 * 1024;
            float2 z0 = *(const float2*)(sm + RS_Z + (r0 * 8 + qn) * 4);
            float2 z1 = *(const float2*)(sm + RS_Z + ((r0 + 8) * 8 + qn) * 4);
            float2 h0 = *(const float2*)(g_h_f32 + h0o);
            float2 h1 = *(const float2*)(g_h_f32 + h1o);
            float n0 = z0.x * h0.x + (1.f - z0.x) * tanhf(x2a.x + acch[0]);
            float n1 = z0.y * h0.y + (1.f - z0.y) * tanhf(x2a.y + acch[1]);
            float n2 = z1.x * h1.x + (1.f - z1.x) * tanhf(x2b.x + acch[2]);
            float n3 = z1.y * h1.y + (1.f - z1.y) * tanhf(x2b.y + acch[3]);
            *(float2*)(out + o0) = make_float2(n0, n1);
            *(float2*)(out + o1) = make_float2(n2, n3);
            *(float2*)(g_h_f32 + h0o) = make_float2(n0, n1);
            *(float2*)(g_h_f32 + h1o) = make_float2(n2, n3);
            __stcg((uint32_t*)(g_h16[pn] + h0o), packh(n0, n1));
            __stcg((uint32_t*)(g_h16[pn] + h1o), packh(n2, n3));
            if (t == TT - 1) {
                size_t f0 = (size_t)TT * BH + h0o;
                *(float2*)(out + f0)            = make_float2(n0, n1);
                *(float2*)(out + f0 + 8 * 1024) = make_float2(n2, n3);
            }
            __threadfence();
        }
        __syncthreads();
        if (tid == 0) red_rel_gpu(&g_cnt_h[mychunk], 1u);     // h slice published
    }
}

// ---------------- launch ---------------------------------------------------
extern "C" void kernel_launch(void* const* d_in, const int* in_sizes, int n_in,
                              void* d_out, int out_size) {
    const float* X    = (const float*)d_in[0];
    const float* state= (const float*)d_in[1];
    const float* W_xr = (const float*)d_in[2];
    const float* W_hr = (const float*)d_in[3];
    const float* b_r  = (const float*)d_in[4];
    const float* W_xz = (const float*)d_in[5];
    const float* W_hz = (const float*)d_in[6];
    const float* b_z  = (const float*)d_in[7];
    const float* W_xh = (const float*)d_in[8];
    const float* W_hh = (const float*)d_in[9];
    const float* b_h  = (const float*)d_in[10];
    float* out = (float*)d_out;

    __nv_bfloat16 *xhi, *xlo, *whi, *wlo;
    cudaGetSymbolAddress((void**)&xhi, g_X_hi);
    cudaGetSymbolAddress((void**)&xlo, g_X_lo);
    cudaGetSymbolAddress((void**)&whi, g_W_hi);
    cudaGetSymbolAddress((void**)&wlo, g_W_lo);

    split_pass<<<(TT * BB * DH / 4 + 255) / 256, 256>>>(X, xhi, xlo, TT * BB * DH / 4);
    split_pass<<<(1048576 / 4 + 255) / 256, 256>>>(W_xr, whi, wlo, 1048576 / 4);
    split_pass<<<(1048576 / 4 + 255) / 256, 256>>>(W_xz, whi + 1048576, wlo + 1048576, 1048576 / 4);
    split_pass<<<(1048576 / 4 + 255) / 256, 256>>>(W_xh, whi + 2097152, wlo + 2097152, 1048576 / 4);

    cudaFuncSetAttribute(input_gemm,
                         cudaFuncAttributeMaxDynamicSharedMemorySize, IG_TOT);
    dim3 g1(4, 256, 3);
    input_gemm<<<g1, 512, IG_TOT>>>(b_r, b_z, b_h);

    cudaFuncSetAttribute(gru_recurrent,
                         cudaFuncAttributeMaxDynamicSharedMemorySize, RS_TOT);
    gru_recurrent<<<NB, 512, RS_TOT>>>(state, W_hr, W_hz, W_hh, out);
}

// round 11
// speedup vs baseline: 1.7834x; 1.1422x over previous
#include <cuda_runtime.h>
#include <cuda_bf16.h>
#include <cuda_fp16.h>
#include <math.h>
#include <stdint.h>

#define TT 512
#define BB 64
#define DH 1024
#define BH (BB*DH)
#define NB 128          // persistent blocks, 1/SM
#define CPB 8           // hidden columns per block

// ---------------- recurrent kernel SMEM layout (bytes) --------------------
// W slabs: 3 x 16384 (WR, WZ, WH) single fp16
#define RS_W    0
#define RS_A    49152      // 2 buffers x 32768 (fp16 h chunk: 64 rows x 512B)
#define RS_ABUF 32768
#define RS_Z    114688     // z gate buf 64x8 f32
#define RS_TOT  116736

// ---------------- input gemm SMEM layout (bytes, per stage) ---------------
#define IG_A    0          // X fp16: 128 rows x 128B
#define IG_WH   16384      // W hi fp16: 64 rows x 512B
#define IG_WL   49152      // W lo fp16
#define IG_STG  81920
#define IG_TOT  163840

// ---------------- device globals ------------------------------------------
__device__ float g_Xr[(size_t)TT * BH];
__device__ float g_Xz[(size_t)TT * BH];
__device__ float g_Xh[(size_t)TT * BH];
__device__ __half g_X16[(size_t)TT * BB * DH];
__device__ __half g_W16h[3u * 1024u * 1024u];
__device__ __half g_W16l[3u * 1024u * 1024u];
__device__ float g_h_f32[BH];
__device__ __half g_h16[4][BH];      // 4-deep h exchange buffers (fp16)
__device__ __half g_Rh16[4][BH];     // 4-deep Rh exchange buffers (fp16)
__device__ unsigned g_cnt_h[4];      // h-producer counters, per 256-col k-chunk
__device__ unsigned g_cnt_rh[4];     // Rh-producer counters, per k-chunk
__device__ unsigned g_p1done;        // blocks done reading h (phase 1)
__device__ unsigned g_p2done;        // blocks done reading Rh (phase 2)
__device__ unsigned g_bar_count = 0;
__device__ volatile unsigned g_bar_gen = 0;

// ---------------- helpers -------------------------------------------------
__device__ __forceinline__ uint32_t smem_u32(const void* p) {
    uint32_t a;
    asm("{ .reg .u64 t; cvta.to.shared.u64 t, %1; cvt.u32.u64 %0, t; }" : "=r"(a) : "l"(p));
    return a;
}
__device__ __forceinline__ void mma16816h(float* c, const uint32_t* a, const uint32_t* b) {
    asm volatile("mma.sync.aligned.m16n8k16.row.col.f32.f16.f16.f32 "
        "{%0,%1,%2,%3}, {%4,%5,%6,%7}, {%8,%9}, {%0,%1,%2,%3};"
        : "+f"(c[0]), "+f"(c[1]), "+f"(c[2]), "+f"(c[3])
        : "r"(a[0]), "r"(a[1]), "r"(a[2]), "r"(a[3]), "r"(b[0]), "r"(b[1]));
}
__device__ __forceinline__ void ldsm_x4(uint32_t* r, uint32_t a) {
    asm volatile("ldmatrix.sync.aligned.m8n8.x4.shared.b16 {%0,%1,%2,%3}, [%4];"
        : "=r"(r[0]), "=r"(r[1]), "=r"(r[2]), "=r"(r[3]) : "r"(a));
}
__device__ __forceinline__ void ldsm_x4t(uint32_t* r, uint32_t a) {
    asm volatile("ldmatrix.sync.aligned.m8n8.x4.trans.shared.b16 {%0,%1,%2,%3}, [%4];"
        : "=r"(r[0]), "=r"(r[1]), "=r"(r[2]), "=r"(r[3]) : "r"(a));
}
#define CPASYNC16(dst, src) asm volatile("cp.async.cg.shared.global [%0], [%1], 16;" :: "r"(dst), "l"(src))
#define CPCOMMIT() asm volatile("cp.async.commit_group;" ::: "memory")
#define CPWAIT1()  asm volatile("cp.async.wait_group 1;" ::: "memory")
#define CPWAIT0()  asm volatile("cp.async.wait_group 0;" ::: "memory")

__device__ __forceinline__ unsigned ld_acq_g(const unsigned* p) {
    unsigned v;
    asm volatile("ld.acquire.gpu.global.u32 %0, [%1];" : "=r"(v) : "l"(p) : "memory");
    return v;
}
__device__ __forceinline__ void waitGE(const unsigned* p, unsigned tgt) {
    while ((int)(ld_acq_g(p) - tgt) < 0) { }
}
__device__ __forceinline__ void red_rel_gpu(unsigned* p, unsigned v) {
    asm volatile("red.release.gpu.global.add.u32 [%0], %1;" :: "l"(p), "r"(v) : "memory");
}

__device__ __forceinline__ uint32_t packh(float x, float y) {
    __half2 hh = __floats2half2_rn(x, y);
    return *(uint32_t*)&hh;
}
__device__ __forceinline__ float sigf(float x) { return 1.0f / (1.0f + expf(-x)); }
__device__ __forceinline__ uint32_t swz32(uint32_t s, uint32_t r) {
    return ((s & 7u) ^ (r & 7u)) | (s & 24u);
}

// ---------------- grid barrier (init only) --------------------------------
__device__ __forceinline__ void gridBarrier() {
    __syncthreads();
    if (threadIdx.x == 0) {
        __threadfence();
        unsigned g = g_bar_gen;
        if (atomicAdd(&g_bar_count, 1u) == (unsigned)(NB - 1)) {
            g_bar_count = 0;
            __threadfence();
            g_bar_gen = g + 1;
        } else {
            while (g_bar_gen == g) { }
        }
        __threadfence();
    }
    __syncthreads();
}

// ---------------- prepass: fp32 -> fp16 single ----------------------------
__global__ void __launch_bounds__(256) split_h1(
    const float* __restrict__ src, __half* __restrict__ dst, int n4)
{
    int i = blockIdx.x * 256 + threadIdx.x;
    if (i >= n4) return;
    float4 v = __ldg((const float4*)src + i);
    ((uint2*)dst)[i] = make_uint2(packh(v.x, v.y), packh(v.z, v.w));
}

// ---------------- prepass: fp32 -> fp16 hi/lo split -----------------------
__global__ void __launch_bounds__(256) split_h2(
    const float* __restrict__ src, __half* __restrict__ hi,
    __half* __restrict__ lo, int n4)
{
    int i = blockIdx.x * 256 + threadIdx.x;
    if (i >= n4) return;
    float4 v = __ldg((const float4*)src + i);
    float f[4] = { v.x, v.y, v.z, v.w };
    uint32_t hh[2], ll[2];
    #pragma unroll
    for (int q = 0; q < 2; q++) {
        __half h0 = __float2half_rn(f[q*2]),   h1 = __float2half_rn(f[q*2+1]);
        __half l0 = __float2half_rn(f[q*2]   - __half2float(h0));
        __half l1 = __float2half_rn(f[q*2+1] - __half2float(h1));
        __half2 ph = __halves2half2(h0, h1), pl = __halves2half2(l0, l1);
        hh[q] = *(uint32_t*)&ph; ll[q] = *(uint32_t*)&pl;
    }
    ((uint2*)hi)[i] = make_uint2(hh[0], hh[1]);
    ((uint2*)lo)[i] = make_uint2(ll[0], ll[1]);
}

// ---------------- input projection GEMM (fp16 HMMA, cp.async pipeline) ----
// grid (4, 256, 3), 512 threads. Tile M=128, N=256, K-chunk 64.
// X single fp16; W fp16 hi + lo (2-term).
__global__ void __launch_bounds__(512, 1) input_gemm(
    const float* __restrict__ br, const float* __restrict__ bz, const float* __restrict__ bh)
{
    extern __shared__ char sm[];
    const uint32_t sb = smem_u32(sm);
    const int z = blockIdx.z;
    const float* bias = (z == 0) ? br : (z == 1) ? bz : bh;
    float* Out = (z == 0) ? g_Xr : (z == 1) ? g_Xz : g_Xh;
    const __half* WHi = g_W16h + (size_t)z * 1048576u;
    const __half* WLo = g_W16l + (size_t)z * 1048576u;

    const int tid = threadIdx.x;
    const int lane = tid & 31, w = tid >> 5;
    const int rowBase = blockIdx.y * 128;
    const int colBase = blockIdx.x * 256;
    const int mw = (w & 3) * 32;
    const int nw = (w >> 2) * 64;

    float acc[2][8][4];
    #pragma unroll
    for (int i = 0; i < 2; i++)
        #pragma unroll
        for (int j = 0; j < 8; j++)
            #pragma unroll
            for (int q = 0; q < 4; q++) acc[i][j][q] = 0.f;

    auto stage = [&](int c, uint32_t bufSm) {
        const int k0 = c * 64;
        // X: 128 rows x 64 fp16 = 1024 x 16B
        #pragma unroll
        for (int it = 0; it < 2; it++) {
            int idx = tid + it * 512;
            int r = idx >> 3, s = idx & 7;
            uint32_t d = bufSm + IG_A + r * 128 + ((s ^ (r & 7)) * 16);
            const __half* g = g_X16 + (size_t)(rowBase + r) * 1024 + k0 + s * 8;
            CPASYNC16(d, g);
        }
        // W hi/lo: 64 rows x 256 fp16 = 2048 x 16B each
        #pragma unroll
        for (int it = 0; it < 4; it++) {
            int idx = tid + it * 512;
            int k = idx >> 5, s = idx & 31;
            uint32_t d = bufSm + IG_WH + k * 512 + swz32(s, k) * 16;
            const __half* g = WHi + (size_t)(k0 + k) * 1024 + colBase + s * 8;
            CPASYNC16(d, g);
            d = bufSm + IG_WL + k * 512 + swz32(s, k) * 16;
            g = WLo + (size_t)(k0 + k) * 1024 + colBase + s * 8;
            CPASYNC16(d, g);
        }
    };

    stage(0, sb + 0);
    CPCOMMIT();

    for (int c = 0; c < 16; c++) {
        const uint32_t cur = sb + (uint32_t)(c & 1) * IG_STG;
        if (c < 15) {
            stage(c + 1, sb + (uint32_t)((c + 1) & 1) * IG_STG);
            CPCOMMIT();
            CPWAIT1();
        } else {
            CPWAIT0();
        }
        __syncthreads();

        #pragma unroll
        for (int ks = 0; ks < 4; ks++) {
            uint32_t ah[2][4];
            #pragma unroll
            for (int i = 0; i < 2; i++) {
                int row = mw + i * 16 + (lane & 15);
                int s = ks * 2 + (lane >> 4);
                uint32_t ab = cur + IG_A + row * 128 + ((s ^ (row & 7)) * 16);
                ldsm_x4(ah[i], ab);
            }
            #pragma unroll
            for (int jp = 0; jp < 4; jp++) {
                int rrow = ks * 16 + (lane & 15);
                int sc = (nw >> 3) + jp * 2 + (lane >> 4);
                uint32_t bb = cur + rrow * 512 + swz32((uint32_t)sc, (uint32_t)rrow) * 16;
                uint32_t bh[4], bl[4];
                ldsm_x4t(bh, bb + IG_WH);
                ldsm_x4t(bl, bb + IG_WL);
                #pragma unroll
                for (int i = 0; i < 2; i++) {
                    mma16816h(acc[i][jp*2+0], ah[i], &bh[0]);
                    mma16816h(acc[i][jp*2+0], ah[i], &bl[0]);
                    mma16816h(acc[i][jp*2+1], ah[i], &bh[2]);
                    mma16816h(acc[i][jp*2+1], ah[i], &bl[2]);
                }
            }
        }
        __syncthreads();
    }

    const int g = lane >> 2, qn = (lane & 3) * 2;
    #pragma unroll
    for (int j = 0; j < 8; j++) {
        int col = colBase + nw + j * 8 + qn;
        float2 bv = *(const float2*)(bias + col);
        #pragma unroll
        for (int i = 0; i < 2; i++) {
            int r0 = rowBase + mw + i * 16 + g;
            *(float2*)(Out + (size_t)r0 * 1024 + col) =
                make_float2(acc[i][j][0] + bv.x, acc[i][j][1] + bv.y);
            *(float2*)(Out + (size_t)(r0 + 8) * 1024 + col) =
                make_float2(acc[i][j][2] + bv.x, acc[i][j][3] + bv.y);
        }
    }
}

// ---------------- recurrent kernel (persistent, dataflow-synced, fp16) ----
// 128 blocks x 512 threads. Warps 0-7 compute; warps 8-15 poll+stream chunks.
// h / Rh cross blocks as single fp16; W held in SMEM as single fp16.
__global__ void __launch_bounds__(512, 1) gru_recurrent(
    const float* __restrict__ state,
    const float* __restrict__ Whr, const float* __restrict__ Whz, const float* __restrict__ Whh,
    float* __restrict__ out)
{
    extern __shared__ char sm[];
    const uint32_t sb = smem_u32(sm);
    const int tid = threadIdx.x;
    const int lane = tid & 31, w = tid >> 5;
    const int bid = blockIdx.x;
    const int cB  = bid * CPB;
    const int mychunk = bid >> 5;      // 4 chunks, 32 publishers each
    const int cstart  = mychunk;       // staggered start chunk

    // ---- reset dataflow counters (block 0) ----
    if (bid == 0 && tid == 0) {
        #pragma unroll
        for (int c = 0; c < 4; c++) { g_cnt_h[c] = 32u; g_cnt_rh[c] = 0u; }
        g_p1done = 0u; g_p2done = 0u;
    }

    // ---- persistent W slabs: [k][8n] rows of 16B, single fp16 ----
    {
        const float* Wm[3] = { Whr, Whz, Whh };
        for (int idx = tid; idx < 8192; idx += 512) {
            int k = idx >> 3, n = idx & 7;
            #pragma unroll
            for (int m = 0; m < 3; m++) {
                float v = Wm[m][(size_t)k * 1024 + cB + n];
                *(__half*)(sm + RS_W + m * 16384 + k * 16 + n * 2) = __float2half_rn(v);
            }
        }
    }
    // ---- init h (buffer 0) ----
    if (tid < 512) {
        int r = tid >> 3, n = tid & 7;
        size_t gi = (size_t)r * 1024 + cB + n;
        float v = state[gi];
        g_h_f32[gi] = v;
        g_h16[0][gi] = __float2half_rn(v);
    }
    gridBarrier();   // publishes resets + weights + h0; the ONLY grid barrier

    const int m0  = (w & 3) * 16;
    const bool isR = (w < 4);
    const int g   = lane >> 2, qn = (lane & 3) * 2;
    const int r0  = m0 + g;
    const int col = cB + qn;
    const uint32_t wsel = sb + RS_W + (isR ? 0 : 1) * 16384;
    const uint32_t whh  = sb + RS_W + 2 * 16384;
    const int ptid = tid - 256;

    auto loadChunk = [&](const __half* src, int c, int b) {
        char* buf = sm + RS_A + b * RS_ABUF;
        const int kbase = c * 256;
        #pragma unroll
        for (int it = 0; it < 8; it++) {
            int idx = ptid + it * 256;       // 0..2047 (64 rows x 32 segs)
            int r = idx >> 5, s = idx & 31;
            uint32_t off = (uint32_t)r * 512 + swz32((uint32_t)s, (uint32_t)r) * 16;
            size_t go = (size_t)r * 1024 + kbase + s * 8;
            *(uint4*)(buf + off) = __ldcg((const uint4*)(src + go));
        }
    };
    // poll chunk-ready, then load (producer warps 8-15, 256 threads)
    auto pollLoad = [&](const __half* src, int c, int b,
                        const unsigned* cnt, unsigned tgt) {
        if (w == 8) waitGE(cnt + c, tgt);
        asm volatile("bar.sync 1, 256;" ::: "memory");
        loadChunk(src, c, b);
    };
    // consume chunk with k-offset of chunk id c from buffer b (single fp16 W)
    auto mmaChunk = [&](float* acc, int b, uint32_t wBase, int c) {
        const uint32_t abase = sb + RS_A + (uint32_t)b * RS_ABUF;
        const int arow = m0 + (lane & 15);
        #pragma unroll
        for (int ks2 = 0; ks2 < 8; ks2++) {
            uint32_t bh[4];
            uint32_t baddr = wBase + (uint32_t)(c * 256 + ks2 * 32 + lane) * 16;
            ldsm_x4t(bh, baddr);
            int s0 = ks2 * 4 + (lane >> 4);
            int s1 = s0 + 2;
            uint32_t a0 = abase + (uint32_t)arow * 512 + swz32((uint32_t)s0, (uint32_t)arow) * 16;
            uint32_t a1 = abase + (uint32_t)arow * 512 + swz32((uint32_t)s1, (uint32_t)arow) * 16;
            uint32_t ah0[4], ah1[4];
            ldsm_x4(ah0, a0);
            ldsm_x4(ah1, a1);
            mma16816h(acc, ah0, &bh[0]);
            mma16816h(acc, ah1, &bh[2]);
        }
    };

    for (int t = 0; t < TT; t++) {
        const unsigned tgt = 32u * (unsigned)(t + 1);
        const int p  = t & 3;          // read buffer (4-deep)
        const int pn = (t + 1) & 3;    // write buffer for h
        const size_t xoffB = (size_t)t * BH + (size_t)r0 * 1024 + col;

        // ================ phase 1: R (warps 0-3) / Z (warps 4-7) ==========
        float acc[4] = {0.f, 0.f, 0.f, 0.f};
        const __half* Hsrc = g_h16[p];
        // prefetch epilogue-1 X inputs (hidden under the MMA loop)
        float2 x1a, x1b;
        if (w < 8) {
            const float* Xsrc = isR ? g_Xr : g_Xz;
            x1a = __ldg((const float2*)(Xsrc + xoffB));
            x1b = __ldg((const float2*)(Xsrc + xoffB + 8 * 1024));
        }
        if (w >= 8) pollLoad(Hsrc, cstart, 0, g_cnt_h, tgt);
        for (int c = 0; c < 4; c++) {
            __syncthreads();
            if (w < 8)      mmaChunk(acc, c & 1, wsel, (cstart + c) & 3);
            else if (c < 3) pollLoad(Hsrc, (cstart + c + 1) & 3, (c + 1) & 1, g_cnt_h, tgt);
            else if (tid == 256) red_rel_gpu(&g_p1done, 1u);   // all h reads done
        }
        // ---- epilogue 1 ----
        if (w < 8) {
            size_t h0o = (size_t)r0 * 1024 + col, h1o = h0o + 8 * 1024;
            if (isR) {
                // WAR: Rh buf p last read in phase 2 of step t-4
                if (t >= 4) waitGE(&g_p2done, 128u * (unsigned)(t - 3));
                float2 h0 = *(const float2*)(g_h_f32 + h0o);
                float2 h1 = *(const float2*)(g_h_f32 + h1o);
                float a0 = sigf(x1a.x + acc[0]) * h0.x;
                float a1 = sigf(x1a.y + acc[1]) * h0.y;
                float a2 = sigf(x1b.x + acc[2]) * h1.x;
                float a3 = sigf(x1b.y + acc[3]) * h1.y;
                __stcg((uint32_t*)(g_Rh16[p] + h0o), packh(a0, a1));
                __stcg((uint32_t*)(g_Rh16[p] + h1o), packh(a2, a3));
                __threadfence();
            } else {
                *(float2*)(sm + RS_Z + (r0 * 8 + qn) * 4) =
                    make_float2(sigf(x1a.x + acc[0]), sigf(x1a.y + acc[1]));
                *(float2*)(sm + RS_Z + ((r0 + 8) * 8 + qn) * 4) =
                    make_float2(sigf(x1b.x + acc[2]), sigf(x1b.y + acc[3]));
            }
        }
        __syncthreads();
        if (tid == 0) red_rel_gpu(&g_cnt_rh[mychunk], 1u);    // Rh slice published

        // ================ phase 2: H_hat (warps 0-3) ======================
        float acch[4] = {0.f, 0.f, 0.f, 0.f};
        const __half* Rsrc = g_Rh16[p];
        float2 x2a, x2b;
        if (w < 4) {
            x2a = __ldg((const float2*)(g_Xh + xoffB));
            x2b = __ldg((const float2*)(g_Xh + xoffB + 8 * 1024));
        }
        if (w >= 8) pollLoad(Rsrc, cstart, 0, g_cnt_rh, tgt);
        for (int c = 0; c < 4; c++) {
            __syncthreads();
            if (w < 4)      mmaChunk(acch, c & 1, whh, (cstart + c) & 3);
            else if (w >= 8) {
                if (c < 3)  pollLoad(Rsrc, (cstart + c + 1) & 3, (c + 1) & 1, g_cnt_rh, tgt);
                else if (tid == 256) red_rel_gpu(&g_p2done, 1u);  // all Rh reads done
            }
        }
        // ---- epilogue 2 ----
        if (w < 4) {
            // WAR: h buf pn last written step t-4, read in phase 1 of step t-3
            if (t >= 3) waitGE(&g_p1done, 128u * (unsigned)(t - 2));
            size_t o0 = xoffB, o1 = xoffB + 8 * 1024;
            size_t h0o = (size_t)r0 * 1024 + col, h1o = h0o + 8 * 1024;
            float2 z0 = *(const float2*)(sm + RS_Z + (r0 * 8 + qn) * 4);
            float2 z1 = *(const float2*)(sm + RS_Z + ((r0 + 8) * 8 + qn) * 4);
            float2 h0 = *(const float2*)(g_h_f32 + h0o);
            float2 h1 = *(const float2*)(g_h_f32 + h1o);
            float n0 = z0.x * h0.x + (1.f - z0.x) * tanhf(x2a.x + acch[0]);
            float n1 = z0.y * h0.y + (1.f - z0.y) * tanhf(x2a.y + acch[1]);
            float n2 = z1.x * h1.x + (1.f - z1.x) * tanhf(x2b.x + acch[2]);
            float n3 = z1.y * h1.y + (1.f - z1.y) * tanhf(x2b.y + acch[3]);
            *(float2*)(out + o0) = make_float2(n0, n1);
            *(float2*)(out + o1) = make_float2(n2, n3);
            *(float2*)(g_h_f32 + h0o) = make_float2(n0, n1);
            *(float2*)(g_h_f32 + h1o) = make_float2(n2, n3);
            __stcg((uint32_t*)(g_h16[pn] + h0o), packh(n0, n1));
            __stcg((uint32_t*)(g_h16[pn] + h1o), packh(n2, n3));
            if (t == TT - 1) {
                size_t f0 = (size_t)TT * BH + h0o;
                *(float2*)(out + f0)            = make_float2(n0, n1);
                *(float2*)(out + f0 + 8 * 1024) = make_float2(n2, n3);
            }
            __threadfence();
        }
        __syncthreads();
        if (tid == 0) red_rel_gpu(&g_cnt_h[mychunk], 1u);     // h slice published
    }
}

// ---------------- launch ---------------------------------------------------
extern "C" void kernel_launch(void* const* d_in, const int* in_sizes, int n_in,
                              void* d_out, int out_size) {
    const float* X    = (const float*)d_in[0];
    const float* state= (const float*)d_in[1];
    const float* W_xr = (const float*)d_in[2];
    const float* W_hr = (const float*)d_in[3];
    const float* b_r  = (const float*)d_in[4];
    const float* W_xz = (const float*)d_in[5];
    const float* W_hz = (const float*)d_in[6];
    const float* b_z  = (const float*)d_in[7];
    const float* W_xh = (const float*)d_in[8];
    const float* W_hh = (const float*)d_in[9];
    const float* b_h  = (const float*)d_in[10];
    float* out = (float*)d_out;

    __half *x16, *whi, *wlo;
    cudaGetSymbolAddress((void**)&x16, g_X16);
    cudaGetSymbolAddress((void**)&whi, g_W16h);
    cudaGetSymbolAddress((void**)&wlo, g_W16l);

    split_h1<<<(TT * BB * DH / 4 + 255) / 256, 256>>>(X, x16, TT * BB * DH / 4);
    split_h2<<<(1048576 / 4 + 255) / 256, 256>>>(W_xr, whi, wlo, 1048576 / 4);
    split_h2<<<(1048576 / 4 + 255) / 256, 256>>>(W_xz, whi + 1048576, wlo + 1048576, 1048576 / 4);
    split_h2<<<(1048576 / 4 + 255) / 256, 256>>>(W_xh, whi + 2097152, wlo + 2097152, 1048576 / 4);

    cudaFuncSetAttribute(input_gemm,
                         cudaFuncAttributeMaxDynamicSharedMemorySize, IG_TOT);
    dim3 g1(4, 256, 3);
    input_gemm<<<g1, 512, IG_TOT>>>(b_r, b_z, b_h);

    cudaFuncSetAttribute(gru_recurrent,
                         cudaFuncAttributeMaxDynamicSharedMemorySize, RS_TOT);
    gru_recurrent<<<NB, 512, RS_TOT>>>(state, W_hr, W_hz, W_hh, out);
}

// round 12
// speedup vs baseline: 1.8296x; 1.0259x over previous
#include <cuda_runtime.h>
#include <cuda_bf16.h>
#include <cuda_fp16.h>
#include <math.h>
#include <stdint.h>

#define TT 512
#define BB 64
#define DH 1024
#define BH (BB*DH)
#define NB 128          // persistent blocks, 1/SM
#define CPB 8           // hidden columns per block

// ---------------- recurrent kernel SMEM layout (bytes) --------------------
// W slabs: 3 x 16384 (WR, WZ, WH) single fp16
#define RS_W    0
#define RS_A    49152      // 2 buffers x 32768 (fp16 h chunk: 64 rows x 512B)
#define RS_ABUF 32768
#define RS_Z    114688     // z gate buf 64x8 f32
#define RS_TOT  116736

// ---------------- input gemm SMEM layout (bytes, per stage) ---------------
#define IG_A    0          // X fp16: 128 rows x 128B
#define IG_WH   16384      // W hi fp16: 64 rows x 512B
#define IG_WL   49152      // W lo fp16
#define IG_STG  81920
#define IG_TOT  163840

// ---------------- device globals ------------------------------------------
__device__ float g_Xr[(size_t)TT * BH];
__device__ float g_Xz[(size_t)TT * BH];
__device__ float g_Xh[(size_t)TT * BH];
__device__ __half g_X16[(size_t)TT * BB * DH];
__device__ __half g_W16h[3u * 1024u * 1024u];
__device__ __half g_W16l[3u * 1024u * 1024u];
__device__ float g_h_f32[BH];
__device__ __half g_h16[4][BH];      // 4-deep h exchange buffers (fp16)
__device__ __half g_Rh16[4][BH];     // 4-deep Rh exchange buffers (fp16)
__device__ unsigned g_cnt_h[4];      // h-warp-publish counters, per 256-col k-chunk
__device__ unsigned g_cnt_rh[4];     // Rh-warp-publish counters, per k-chunk
__device__ unsigned g_p1done;        // blocks done reading h (phase 1)
__device__ unsigned g_p2done;        // blocks done reading Rh (phase 2)
__device__ unsigned g_bar_count = 0;
__device__ volatile unsigned g_bar_gen = 0;

// ---------------- helpers -------------------------------------------------
__device__ __forceinline__ uint32_t smem_u32(const void* p) {
    uint32_t a;
    asm("{ .reg .u64 t; cvta.to.shared.u64 t, %1; cvt.u32.u64 %0, t; }" : "=r"(a) : "l"(p));
    return a;
}
__device__ __forceinline__ void mma16816h(float* c, const uint32_t* a, const uint32_t* b) {
    asm volatile("mma.sync.aligned.m16n8k16.row.col.f32.f16.f16.f32 "
        "{%0,%1,%2,%3}, {%4,%5,%6,%7}, {%8,%9}, {%0,%1,%2,%3};"
        : "+f"(c[0]), "+f"(c[1]), "+f"(c[2]), "+f"(c[3])
        : "r"(a[0]), "r"(a[1]), "r"(a[2]), "r"(a[3]), "r"(b[0]), "r"(b[1]));
}
__device__ __forceinline__ void ldsm_x4(uint32_t* r, uint32_t a) {
    asm volatile("ldmatrix.sync.aligned.m8n8.x4.shared.b16 {%0,%1,%2,%3}, [%4];"
        : "=r"(r[0]), "=r"(r[1]), "=r"(r[2]), "=r"(r[3]) : "r"(a));
}
__device__ __forceinline__ void ldsm_x4t(uint32_t* r, uint32_t a) {
    asm volatile("ldmatrix.sync.aligned.m8n8.x4.trans.shared.b16 {%0,%1,%2,%3}, [%4];"
        : "=r"(r[0]), "=r"(r[1]), "=r"(r[2]), "=r"(r[3]) : "r"(a));
}
#define CPASYNC16(dst, src) asm volatile("cp.async.cg.shared.global [%0], [%1], 16;" :: "r"(dst), "l"(src))
#define CPCOMMIT() asm volatile("cp.async.commit_group;" ::: "memory")
#define CPWAIT1()  asm volatile("cp.async.wait_group 1;" ::: "memory")
#define CPWAIT0()  asm volatile("cp.async.wait_group 0;" ::: "memory")

__device__ __forceinline__ unsigned ld_acq_g(const unsigned* p) {
    unsigned v;
    asm volatile("ld.acquire.gpu.global.u32 %0, [%1];" : "=r"(v) : "l"(p) : "memory");
    return v;
}
__device__ __forceinline__ void waitGE(const unsigned* p, unsigned tgt) {
    while ((int)(ld_acq_g(p) - tgt) < 0) { }
}
__device__ __forceinline__ void red_rel_gpu(unsigned* p, unsigned v) {
    asm volatile("red.release.gpu.global.add.u32 [%0], %1;" :: "l"(p), "r"(v) : "memory");
}

__device__ __forceinline__ uint32_t packh(float x, float y) {
    __half2 hh = __floats2half2_rn(x, y);
    return *(uint32_t*)&hh;
}
__device__ __forceinline__ float sigf(float x) { return 1.0f / (1.0f + expf(-x)); }
__device__ __forceinline__ uint32_t swz32(uint32_t s, uint32_t r) {
    return ((s & 7u) ^ (r & 7u)) | (s & 24u);
}

// ---------------- grid barrier (init only) --------------------------------
__device__ __forceinline__ void gridBarrier() {
    __syncthreads();
    if (threadIdx.x == 0) {
        __threadfence();
        unsigned g = g_bar_gen;
        if (atomicAdd(&g_bar_count, 1u) == (unsigned)(NB - 1)) {
            g_bar_count = 0;
            __threadfence();
            g_bar_gen = g + 1;
        } else {
            while (g_bar_gen == g) { }
        }
        __threadfence();
    }
    __syncthreads();
}

// ---------------- prepass: fp32 -> fp16 single ----------------------------
__global__ void __launch_bounds__(256) split_h1(
    const float* __restrict__ src, __half* __restrict__ dst, int n4)
{
    int i = blockIdx.x * 256 + threadIdx.x;
    if (i >= n4) return;
    float4 v = __ldg((const float4*)src + i);
    ((uint2*)dst)[i] = make_uint2(packh(v.x, v.y), packh(v.z, v.w));
}

// ---------------- prepass: fp32 -> fp16 hi/lo split -----------------------
__global__ void __launch_bounds__(256) split_h2(
    const float* __restrict__ src, __half* __restrict__ hi,
    __half* __restrict__ lo, int n4)
{
    int i = blockIdx.x * 256 + threadIdx.x;
    if (i >= n4) return;
    float4 v = __ldg((const float4*)src + i);
    float f[4] = { v.x, v.y, v.z, v.w };
    uint32_t hh[2], ll[2];
    #pragma unroll
    for (int q = 0; q < 2; q++) {
        __half h0 = __float2half_rn(f[q*2]),   h1 = __float2half_rn(f[q*2+1]);
        __half l0 = __float2half_rn(f[q*2]   - __half2float(h0));
        __half l1 = __float2half_rn(f[q*2+1] - __half2float(h1));
        __half2 ph = __halves2half2(h0, h1), pl = __halves2half2(l0, l1);
        hh[q] = *(uint32_t*)&ph; ll[q] = *(uint32_t*)&pl;
    }
    ((uint2*)hi)[i] = make_uint2(hh[0], hh[1]);
    ((uint2*)lo)[i] = make_uint2(ll[0], ll[1]);
}

// ---------------- input projection GEMM (fp16 HMMA, cp.async pipeline) ----
__global__ void __launch_bounds__(512, 1) input_gemm(
    const float* __restrict__ br, const float* __restrict__ bz, const float* __restrict__ bh)
{
    extern __shared__ char sm[];
    const uint32_t sb = smem_u32(sm);
    const int z = blockIdx.z;
    const float* bias = (z == 0) ? br : (z == 1) ? bz : bh;
    float* Out = (z == 0) ? g_Xr : (z == 1) ? g_Xz : g_Xh;
    const __half* WHi = g_W16h + (size_t)z * 1048576u;
    const __half* WLo = g_W16l + (size_t)z * 1048576u;

    const int tid = threadIdx.x;
    const int lane = tid & 31, w = tid >> 5;
    const int rowBase = blockIdx.y * 128;
    const int colBase = blockIdx.x * 256;
    const int mw = (w & 3) * 32;
    const int nw = (w >> 2) * 64;

    float acc[2][8][4];
    #pragma unroll
    for (int i = 0; i < 2; i++)
        #pragma unroll
        for (int j = 0; j < 8; j++)
            #pragma unroll
            for (int q = 0; q < 4; q++) acc[i][j][q] = 0.f;

    auto stage = [&](int c, uint32_t bufSm) {
        const int k0 = c * 64;
        #pragma unroll
        for (int it = 0; it < 2; it++) {
            int idx = tid + it * 512;
            int r = idx >> 3, s = idx & 7;
            uint32_t d = bufSm + IG_A + r * 128 + ((s ^ (r & 7)) * 16);
            const __half* g = g_X16 + (size_t)(rowBase + r) * 1024 + k0 + s * 8;
            CPASYNC16(d, g);
        }
        #pragma unroll
        for (int it = 0; it < 4; it++) {
            int idx = tid + it * 512;
            int k = idx >> 5, s = idx & 31;
            uint32_t d = bufSm + IG_WH + k * 512 + swz32(s, k) * 16;
            const __half* g = WHi + (size_t)(k0 + k) * 1024 + colBase + s * 8;
            CPASYNC16(d, g);
            d = bufSm + IG_WL + k * 512 + swz32(s, k) * 16;
            g = WLo + (size_t)(k0 + k) * 1024 + colBase + s * 8;
            CPASYNC16(d, g);
        }
    };

    stage(0, sb + 0);
    CPCOMMIT();

    for (int c = 0; c < 16; c++) {
        const uint32_t cur = sb + (uint32_t)(c & 1) * IG_STG;
        if (c < 15) {
            stage(c + 1, sb + (uint32_t)((c + 1) & 1) * IG_STG);
            CPCOMMIT();
            CPWAIT1();
        } else {
            CPWAIT0();
        }
        __syncthreads();

        #pragma unroll
        for (int ks = 0; ks < 4; ks++) {
            uint32_t ah[2][4];
            #pragma unroll
            for (int i = 0; i < 2; i++) {
                int row = mw + i * 16 + (lane & 15);
                int s = ks * 2 + (lane >> 4);
                uint32_t ab = cur + IG_A + row * 128 + ((s ^ (row & 7)) * 16);
                ldsm_x4(ah[i], ab);
            }
            #pragma unroll
            for (int jp = 0; jp < 4; jp++) {
                int rrow = ks * 16 + (lane & 15);
                int sc = (nw >> 3) + jp * 2 + (lane >> 4);
                uint32_t bb = cur + rrow * 512 + swz32((uint32_t)sc, (uint32_t)rrow) * 16;
                uint32_t bh[4], bl[4];
                ldsm_x4t(bh, bb + IG_WH);
                ldsm_x4t(bl, bb + IG_WL);
                #pragma unroll
                for (int i = 0; i < 2; i++) {
                    mma16816h(acc[i][jp*2+0], ah[i], &bh[0]);
                    mma16816h(acc[i][jp*2+0], ah[i], &bl[0]);
                    mma16816h(acc[i][jp*2+1], ah[i], &bh[2]);
                    mma16816h(acc[i][jp*2+1], ah[i], &bl[2]);
                }
            }
        }
        __syncthreads();
    }

    const int g = lane >> 2, qn = (lane & 3) * 2;
    #pragma unroll
    for (int j = 0; j < 8; j++) {
        int col = colBase + nw + j * 8 + qn;
        float2 bv = *(const float2*)(bias + col);
        #pragma unroll
        for (int i = 0; i < 2; i++) {
            int r0 = rowBase + mw + i * 16 + g;
            *(float2*)(Out + (size_t)r0 * 1024 + col) =
                make_float2(acc[i][j][0] + bv.x, acc[i][j][1] + bv.y);
            *(float2*)(Out + (size_t)(r0 + 8) * 1024 + col) =
                make_float2(acc[i][j][2] + bv.x, acc[i][j][3] + bv.y);
        }
    }
}

// ---------------- recurrent kernel (persistent, per-warp early publish) ---
// 128 blocks x 512 threads. Warps 0-7 compute; warps 8-15 poll+stream chunks.
// Publishing warps release their own slice + counter immediately (no block sync).
__global__ void __launch_bounds__(512, 1) gru_recurrent(
    const float* __restrict__ state,
    const float* __restrict__ Whr, const float* __restrict__ Whz, const float* __restrict__ Whh,
    float* __restrict__ out)
{
    extern __shared__ char sm[];
    const uint32_t sb = smem_u32(sm);
    const int tid = threadIdx.x;
    const int lane = tid & 31, w = tid >> 5;
    const int bid = blockIdx.x;
    const int cB  = bid * CPB;
    const int mychunk = bid >> 5;      // 4 chunks, 32 blocks (128 warps) each
    const int cstart  = mychunk;       // staggered start chunk

    // ---- reset dataflow counters (block 0) ----
    if (bid == 0 && tid == 0) {
        #pragma unroll
        for (int c = 0; c < 4; c++) { g_cnt_h[c] = 128u; g_cnt_rh[c] = 0u; }
        g_p1done = 0u; g_p2done = 0u;
    }

    // ---- persistent W slabs: [k][8n] rows of 16B, single fp16 ----
    {
        const float* Wm[3] = { Whr, Whz, Whh };
        for (int idx = tid; idx < 8192; idx += 512) {
            int k = idx >> 3, n = idx & 7;
            #pragma unroll
            for (int m = 0; m < 3; m++) {
                float v = Wm[m][(size_t)k * 1024 + cB + n];
                *(__half*)(sm + RS_W + m * 16384 + k * 16 + n * 2) = __float2half_rn(v);
            }
        }
    }
    // ---- init h (buffer 0) ----
    if (tid < 512) {
        int r = tid >> 3, n = tid & 7;
        size_t gi = (size_t)r * 1024 + cB + n;
        float v = state[gi];
        g_h_f32[gi] = v;
        g_h16[0][gi] = __float2half_rn(v);
    }
    gridBarrier();   // publishes resets + weights + h0; the ONLY grid barrier

    const int m0  = (w & 3) * 16;
    const bool isR = (w < 4);
    const int g   = lane >> 2, qn = (lane & 3) * 2;
    const int r0  = m0 + g;
    const int col = cB + qn;
    const uint32_t wsel = sb + RS_W + (isR ? 0 : 1) * 16384;
    const uint32_t whh  = sb + RS_W + 2 * 16384;
    const int ptid = tid - 256;

    auto loadChunk = [&](const __half* src, int c, int b) {
        char* buf = sm + RS_A + b * RS_ABUF;
        const int kbase = c * 256;
        #pragma unroll
        for (int it = 0; it < 8; it++) {
            int idx = ptid + it * 256;       // 0..2047 (64 rows x 32 segs)
            int r = idx >> 5, s = idx & 31;
            uint32_t off = (uint32_t)r * 512 + swz32((uint32_t)s, (uint32_t)r) * 16;
            size_t go = (size_t)r * 1024 + kbase + s * 8;
            *(uint4*)(buf + off) = __ldcg((const uint4*)(src + go));
        }
    };
    // poll chunk-ready, then load (producer warps 8-15, 256 threads)
    auto pollLoad = [&](const __half* src, int c, int b,
                        const unsigned* cnt, unsigned tgt) {
        if (w == 8) waitGE(cnt + c, tgt);
        asm volatile("bar.sync 1, 256;" ::: "memory");
        loadChunk(src, c, b);
    };
    // consume chunk with k-offset of chunk id c from buffer b (single fp16 W)
    auto mmaChunk = [&](float* acc, int b, uint32_t wBase, int c) {
        const uint32_t abase = sb + RS_A + (uint32_t)b * RS_ABUF;
        const int arow = m0 + (lane & 15);
        #pragma unroll
        for (int ks2 = 0; ks2 < 8; ks2++) {
            uint32_t bh[4];
            uint32_t baddr = wBase + (uint32_t)(c * 256 + ks2 * 32 + lane) * 16;
            ldsm_x4t(bh, baddr);
            int s0 = ks2 * 4 + (lane >> 4);
            int s1 = s0 + 2;
            uint32_t a0 = abase + (uint32_t)arow * 512 + swz32((uint32_t)s0, (uint32_t)arow) * 16;
            uint32_t a1 = abase + (uint32_t)arow * 512 + swz32((uint32_t)s1, (uint32_t)arow) * 16;
            uint32_t ah0[4], ah1[4];
            ldsm_x4(ah0, a0);
            ldsm_x4(ah1, a1);
            mma16816h(acc, ah0, &bh[0]);
            mma16816h(acc, ah1, &bh[2]);
        }
    };

    for (int t = 0; t < TT; t++) {
        const unsigned tgt = 128u * (unsigned)(t + 1);
        const int p  = t & 3;          // read buffer (4-deep)
        const int pn = (t + 1) & 3;    // write buffer for h
        const size_t xoffB = (size_t)t * BH + (size_t)r0 * 1024 + col;

        // ================ phase 1: R (warps 0-3) / Z (warps 4-7) ==========
        float acc[4] = {0.f, 0.f, 0.f, 0.f};
        const __half* Hsrc = g_h16[p];
        // prefetch epilogue-1 X inputs (hidden under the MMA loop)
        float2 x1a, x1b;
        if (w < 8) {
            const float* Xsrc = isR ? g_Xr : g_Xz;
            x1a = __ldg((const float2*)(Xsrc + xoffB));
            x1b = __ldg((const float2*)(Xsrc + xoffB + 8 * 1024));
        }
        if (w >= 8) pollLoad(Hsrc, cstart, 0, g_cnt_h, tgt);
        for (int c = 0; c < 4; c++) {
            __syncthreads();
            if (w < 8)      mmaChunk(acc, c & 1, wsel, (cstart + c) & 3);
            else if (c < 3) pollLoad(Hsrc, (cstart + c + 1) & 3, (c + 1) & 1, g_cnt_h, tgt);
            else if (tid == 256) red_rel_gpu(&g_p1done, 1u);   // all h reads done
        }
        // ---- epilogue 1 (per-warp early publish of Rh) ----
        if (w < 8) {
            size_t h0o = (size_t)r0 * 1024 + col, h1o = h0o + 8 * 1024;
            if (isR) {
                // WAR: Rh buf p last read in phase 2 of step t-4
                if (t >= 4) waitGE(&g_p2done, 128u * (unsigned)(t - 3));
                float2 h0 = *(const float2*)(g_h_f32 + h0o);
                float2 h1 = *(const float2*)(g_h_f32 + h1o);
                float a0 = sigf(x1a.x + acc[0]) * h0.x;
                float a1 = sigf(x1a.y + acc[1]) * h0.y;
                float a2 = sigf(x1b.x + acc[2]) * h1.x;
                float a3 = sigf(x1b.y + acc[3]) * h1.y;
                __stcg((uint32_t*)(g_Rh16[p] + h0o), packh(a0, a1));
                __stcg((uint32_t*)(g_Rh16[p] + h1o), packh(a2, a3));
                __syncwarp();
                if (lane == 0) red_rel_gpu(&g_cnt_rh[mychunk], 1u);
            } else {
                *(float2*)(sm + RS_Z + (r0 * 8 + qn) * 4) =
                    make_float2(sigf(x1a.x + acc[0]), sigf(x1a.y + acc[1]));
                *(float2*)(sm + RS_Z + ((r0 + 8) * 8 + qn) * 4) =
                    make_float2(sigf(x1b.x + acc[2]), sigf(x1b.y + acc[3]));
            }
        }

        // ================ phase 2: H_hat (warps 0-3) ======================
        float acch[4] = {0.f, 0.f, 0.f, 0.f};
        const __half* Rsrc = g_Rh16[p];
        float2 x2a, x2b;
        if (w < 4) {
            x2a = __ldg((const float2*)(g_Xh + xoffB));
            x2b = __ldg((const float2*)(g_Xh + xoffB + 8 * 1024));
        }
        if (w >= 8) pollLoad(Rsrc, cstart, 0, g_cnt_rh, tgt);
        for (int c = 0; c < 4; c++) {
            __syncthreads();
            if (w < 4)      mmaChunk(acch, c & 1, whh, (cstart + c) & 3);
            else if (w >= 8) {
                if (c < 3)  pollLoad(Rsrc, (cstart + c + 1) & 3, (c + 1) & 1, g_cnt_rh, tgt);
                else if (tid == 256) red_rel_gpu(&g_p2done, 1u);  // all Rh reads done
            }
        }
        // ---- epilogue 2 (per-warp early publish of h) ----
        if (w < 4) {
            // WAR: h buf pn last written step t-4, read in phase 1 of step t-3
            if (t >= 3) waitGE(&g_p1done, 128u * (unsigned)(t - 2));
            size_t o0 = xoffB, o1 = xoffB + 8 * 1024;
            size_t h0o = (size_t)r0 * 1024 + col, h1o = h0o + 8 * 1024;
            float2 z0 = *(const float2*)(sm + RS_Z + (r0 * 8 + qn) * 4);
            float2 z1 = *(const float2*)(sm + RS_Z + ((r0 + 8) * 8 + qn) * 4);
            float2 h0 = *(const float2*)(g_h_f32 + h0o);
            float2 h1 = *(const float2*)(g_h_f32 + h1o);
            float n0 = z0.x * h0.x + (1.f - z0.x) * tanhf(x2a.x + acch[0]);
            float n1 = z0.y * h0.y + (1.f - z0.y) * tanhf(x2a.y + acch[1]);
            float n2 = z1.x * h1.x + (1.f - z1.x) * tanhf(x2b.x + acch[2]);
            float n3 = z1.y * h1.y + (1.f - z1.y) * tanhf(x2b.y + acch[3]);
            __stcg((uint32_t*)(g_h16[pn] + h0o), packh(n0, n1));
            __stcg((uint32_t*)(g_h16[pn] + h1o), packh(n2, n3));
            __syncwarp();
            if (lane == 0) red_rel_gpu(&g_cnt_h[mychunk], 1u);
            *(float2*)(out + o0) = make_float2(n0, n1);
            *(float2*)(out + o1) = make_float2(n2, n3);
            *(float2*)(g_h_f32 + h0o) = make_float2(n0, n1);
            *(float2*)(g_h_f32 + h1o) = make_float2(n2, n3);
            if (t == TT - 1) {
                size_t f0 = (size_t)TT * BH + h0o;
                *(float2*)(out + f0)            = make_float2(n0, n1);
                *(float2*)(out + f0 + 8 * 1024) = make_float2(n2, n3);
            }
        }
    }
}

// ---------------- launch ---------------------------------------------------
extern "C" void kernel_launch(void* const* d_in, const int* in_sizes, int n_in,
                              void* d_out, int out_size) {
    const float* X    = (const float*)d_in[0];
    const float* state= (const float*)d_in[1];
    const float* W_xr = (const float*)d_in[2];
    const float* W_hr = (const float*)d_in[3];
    const float* b_r  = (const float*)d_in[4];
    const float* W_xz = (const float*)d_in[5];
    const float* W_hz = (const float*)d_in[6];
    const float* b_z  = (const float*)d_in[7];
    const float* W_xh = (const float*)d_in[8];
    const float* W_hh = (const float*)d_in[9];
    const float* b_h  = (const float*)d_in[10];
    float* out = (float*)d_out;

    __half *x16, *whi, *wlo;
    cudaGetSymbolAddress((void**)&x16, g_X16);
    cudaGetSymbolAddress((void**)&whi, g_W16h);
    cudaGetSymbolAddress((void**)&wlo, g_W16l);

    split_h1<<<(TT * BB * DH / 4 + 255) / 256, 256>>>(X, x16, TT * BB * DH / 4);
    split_h2<<<(1048576 / 4 + 255) / 256, 256>>>(W_xr, whi, wlo, 1048576 / 4);
    split_h2<<<(1048576 / 4 + 255) / 256, 256>>>(W_xz, whi + 1048576, wlo + 1048576, 1048576 / 4);
    split_h2<<<(1048576 / 4 + 255) / 256, 256>>>(W_xh, whi + 2097152, wlo + 2097152, 1048576 / 4);

    cudaFuncSetAttribute(input_gemm,
                         cudaFuncAttributeMaxDynamicSharedMemorySize, IG_TOT);
    dim3 g1(4, 256, 3);
    input_gemm<<<g1, 512, IG_TOT>>>(b_r, b_z, b_h);

    cudaFuncSetAttribute(gru_recurrent,
                         cudaFuncAttributeMaxDynamicSharedMemorySize, RS_TOT);
    gru_recurrent<<<NB, 512, RS_TOT>>>(state, W_hr, W_hz, W_hh, out);
}